// round 9
// baseline (speedup 1.0000x reference)
#include <cuda_runtime.h>
#include <cuda_bf16.h>
#include <cstdint>

// Problem dims (fixed by the dataset)
#define N_   64
#define C_   64
#define T_   300
#define V_   25
#define S_   3
#define TT   4              // t positions per block
#define COLS 100            // TT*V_
#define TBLK 75             // T_/TT
#define NTHREADS 256

// -------- global folded parameters (written by prep kernel) --------
__device__ __align__(16) uint4 g_Wf[S_ * 4 * 8 * 32];   // W frags [s][kt][ntg][lane]
__device__ __align__(16) uint4 g_Af[S_ * 2 * 2 * 2 * 32]; // Ae^T frags [s][mt][kt][hl][lane]
__device__ __align__(16) float g_ab[128];                // alpha | bshift

// ---------------- bf16 / mma helpers ----------------
// packbf(hi_elem, lo_elem): low 16 bits = bf16(lo_elem)
__device__ __forceinline__ uint32_t packbf(float hi, float lo) {
    uint32_t d;
    asm("cvt.rn.bf16x2.f32 %0, %1, %2;" : "=r"(d) : "f"(hi), "f"(lo));
    return d;
}
__device__ __forceinline__ void mma16816(float* c, const uint32_t* a,
                                         uint32_t b0, uint32_t b1) {
    asm volatile(
        "mma.sync.aligned.m16n8k16.row.col.f32.bf16.bf16.f32 "
        "{%0,%1,%2,%3}, {%4,%5,%6,%7}, {%8,%9}, {%0,%1,%2,%3};"
        : "+f"(c[0]), "+f"(c[1]), "+f"(c[2]), "+f"(c[3])
        : "r"(a[0]), "r"(a[1]), "r"(a[2]), "r"(a[3]), "r"(b0), "r"(b1));
}
__device__ __forceinline__ void ldsm_x4(uint32_t* r, uint32_t addr) {
    asm volatile(
        "ldmatrix.sync.aligned.m8n8.x4.shared.b16 {%0,%1,%2,%3}, [%4];"
        : "=r"(r[0]), "=r"(r[1]), "=r"(r[2]), "=r"(r[3]) : "r"(addr));
}
__device__ __forceinline__ uint32_t smem_u32_of(const void* p) {
    uint32_t a;
    asm("{ .reg .u64 t; cvta.to.shared.u64 t, %1; cvt.u32.u64 %0, t; }"
        : "=r"(a) : "l"(p));
    return a;
}

// ---------------- prep: fold params (tiny, few blocks) ----------------
__global__ void unit_gcn_prep(const float* __restrict__ pA,
                              const float* __restrict__ pPA1,
                              const float* __restrict__ pPA2,
                              const float* __restrict__ pWc,
                              const float* __restrict__ pbc,
                              const float* __restrict__ pgamma,
                              const float* __restrict__ pbeta,
                              const float* __restrict__ prmean,
                              const float* __restrict__ prvar) {
    int tid = blockIdx.x * blockDim.x + threadIdx.x;

    // W fragments for GEMM2 B operand (col-major KxN), hi/lo bf16.
    for (int i = tid; i < S_ * 4 * 8 * 32; i += blockDim.x * gridDim.x) {
        int lane = i & 31;
        int ntg  = (i >> 5) & 7;
        int kt   = (i >> 8) & 3;
        int s    = i >> 10;
        int n  = ntg * 8 + (lane >> 2);
        int k0 = kt * 16 + (lane & 3) * 2;
        const float* wr = pWc + (s * 64 + n) * 64;
        float w0 = wr[k0], w1 = wr[k0 + 1], w8 = wr[k0 + 8], w9 = wr[k0 + 9];
        uint32_t h01 = packbf(w1, w0);
        uint32_t h89 = packbf(w9, w8);
        float r0 = w0 - __uint_as_float(h01 << 16);
        float r1 = w1 - __uint_as_float(h01 & 0xffff0000u);
        float r8 = w8 - __uint_as_float(h89 << 16);
        float r9 = w9 - __uint_as_float(h89 & 0xffff0000u);
        uint4 frag;
        frag.x = h01;
        frag.y = h89;
        frag.z = packbf(r1, r0);
        frag.w = packbf(r9, r8);
        g_Wf[i] = frag;
    }

    // Ae^T fragments for GEMM1 A operand (row-major 32x32, m=w, k=v), hi/lo.
    for (int i = tid; i < S_ * 2 * 2 * 2 * 32; i += blockDim.x * gridDim.x) {
        int lane = i & 31;
        int hl = (i >> 5) & 1;
        int kt = (i >> 6) & 1;
        int mt = (i >> 7) & 1;
        int s  = i >> 8;
        int gm = mt * 16 + (lane >> 2);
        int k0 = kt * 16 + (lane & 3) * 2;
        float e[8];
        int ms[2] = {gm, gm + 8};
        int ks[4] = {k0, k0 + 1, k0 + 8, k0 + 9};
#pragma unroll
        for (int kk = 0; kk < 4; kk++)
#pragma unroll
            for (int mm = 0; mm < 2; mm++) {
                int m = ms[mm], k = ks[kk];
                float v = 0.0f;
                if (m < V_ && k < V_) {
                    int idx = (s * V_ + k) * V_ + m;
                    v = pA[idx] * pPA1[idx] + pPA2[idx];
                }
                e[kk * 2 + mm] = v;
            }
        if (hl) {
#pragma unroll
            for (int q = 0; q < 8; q++) {
                float h = __bfloat162float(__float2bfloat16(e[q]));
                e[q] = e[q] - h;
            }
        }
        uint4 frag;
        frag.x = packbf(e[2], e[0]);
        frag.y = packbf(e[3], e[1]);
        frag.z = packbf(e[6], e[4]);
        frag.w = packbf(e[7], e[5]);
        g_Af[i] = frag;
    }

    // BN fold: out = gemm*alpha + bshift (+x, relu). Bias folded into bshift.
    if (tid < C_) {
        float sc = pgamma[tid] / sqrtf(prvar[tid] + 1e-5f);
        float btot = pbc[tid] + pbc[64 + tid] + pbc[128 + tid];
        g_ab[tid] = sc;
        g_ab[64 + tid] = btot * sc + (pbeta[tid] - prmean[tid] * sc);
    }
}

// ---------------- main fused kernel ----------------
// smem layout (float index). A2 double-buffered: [m][kw], 36-word rows (144B),
// conflict-free for both ldmatrix and the pack stores (verified bank math).
#define AB_O    0                     // 128: alpha|bshift
#define A2H0_O  128                   // 4032
#define A2L0_O  4160                  // 4032
#define A2H1_O  8192                  // 4032
#define A2L1_O  12224                 // 4032
#define XBH_O   16256                 // 16 x 264 = 4224 (GEMM1 B hi)
#define XBL_O   20480                 // 4224 (lo)
#define SCR_O   XBH_O                 // epilogue scratch [o][108] overlays xb
#define SMEM_FLOATS 24704
#define SMEM_BYTES  (SMEM_FLOATS * 4) // 98816 -> 2 CTAs/SM

__global__ void __launch_bounds__(NTHREADS, 2)
unit_gcn_main(const float* __restrict__ x, float* __restrict__ out) {
    const int n  = blockIdx.y;
    const int bx = blockIdx.x;       // t-tile
    const int tid = threadIdx.x;
    const int wid = tid >> 5;
    const int lane = tid & 31;

    extern __shared__ float sm[];
    float* ab = sm + AB_O;
    uint32_t* xbh = (uint32_t*)(sm + XBH_O);
    uint32_t* xbl = (uint32_t*)(sm + XBL_O);

    // Stage BN constants
    if (tid < 128) ab[tid] = g_ab[tid];

    // Zero xb pad rows 12..15 (v >= 25 region; v=24 lands in row 12 half 0)
    for (int i = tid; i < 4 * 264; i += NTHREADS) {
        xbh[12 * 264 + i] = 0u;
        xbl[12 * 264 + i] = 0u;
    }
    __syncthreads();   // pad-zero must precede staging writes into row 12

    // Stage x tile as k-packed bf16 hi/lo for GEMM1 B.
    {
        const float4* xp = (const float4*)x;
        __nv_bfloat16* bh = (__nv_bfloat16*)xbh;
        __nv_bfloat16* bl = (__nv_bfloat16*)xbl;
        for (int q = tid; q < 1600; q += NTHREADS) {
            int c = q / 25;
            int f = q % 25;
            float4 val = xp[(n * 64 + c) * 1875 + bx * 25 + f];
            int p0 = f * 4;
            float vv[4] = {val.x, val.y, val.z, val.w};
#pragma unroll
            for (int j = 0; j < 4; j++) {
                int p = p0 + j;
                int tt = p / 25;
                int w = p - tt * 25;        // joint index v
                float v = vv[j];
                __nv_bfloat16 h = __float2bfloat16(v);
                __nv_bfloat16 l = __float2bfloat16(v - __bfloat162float(h));
                int half = ((w >> 1) * 264 + tt * 64 + c) * 2 + (w & 1);
                bh[half] = h;
                bl[half] = l;
            }
        }
    }
    __syncthreads();

    // GEMM2 warp coords: wy -> m rows, wx -> n channels
    const int wy = wid & 3;
    const int wx = wid >> 2;

    float acc[2][4][4];
#pragma unroll
    for (int i = 0; i < 2; i++)
#pragma unroll
        for (int j = 0; j < 4; j++)
#pragma unroll
            for (int q = 0; q < 4; q++) acc[i][j][q] = 0.0f;

    // ldmatrix lane addressing (A2 buffer 0 base in u32 shared space)
    const uint32_t a2h0_u = smem_u32_of(sm + A2H0_O);
    const uint32_t a2dlt = (uint32_t)((A2L0_O - A2H0_O) * 4);   // hi->lo
    const uint32_t a2buf = (uint32_t)((A2H1_O - A2H0_O) * 4);   // buf0->buf1
    const uint32_t lds_lane_off = (uint32_t)((lane & 15) * 144 + (lane >> 4) * 16);

#pragma unroll
    for (int s = 0; s < S_; s++) {
        uint32_t* a2h = (uint32_t*)(sm + ((s & 1) ? A2H1_O : A2H0_O));
        uint32_t* a2l = (uint32_t*)(sm + ((s & 1) ? A2L1_O : A2L0_O));

        // ======== GEMM1: D1[w, tt*64+c] = Ae^T . xs  (M=32,N=256,K=32) ========
        // warp owns n-slice [wid*32, wid*32+32)
        {
            uint4 AH[2][2], AL[2][2];
#pragma unroll
            for (int mt = 0; mt < 2; mt++)
#pragma unroll
                for (int kt = 0; kt < 2; kt++) {
                    AH[mt][kt] = __ldg(g_Af + ((((s * 2 + mt) * 2 + kt) * 2 + 0) * 32) + lane);
                    AL[mt][kt] = __ldg(g_Af + ((((s * 2 + mt) * 2 + kt) * 2 + 1) * 32) + lane);
                }

            float d1[2][4][4];
#pragma unroll
            for (int i = 0; i < 2; i++)
#pragma unroll
                for (int j = 0; j < 4; j++)
#pragma unroll
                    for (int q = 0; q < 4; q++) d1[i][j][q] = 0.0f;

#pragma unroll
            for (int kt = 0; kt < 2; kt++) {
                const int rb = kt * 8 + (lane & 3);
#pragma unroll
                for (int nt = 0; nt < 4; nt++) {
                    const int nn = wid * 32 + nt * 8 + (lane >> 2);
                    uint32_t bh0 = xbh[rb * 264 + nn];
                    uint32_t bh1 = xbh[(rb + 4) * 264 + nn];
                    uint32_t bl0 = xbl[rb * 264 + nn];
                    uint32_t bl1 = xbl[(rb + 4) * 264 + nn];
#pragma unroll
                    for (int mt = 0; mt < 2; mt++) {
                        mma16816(d1[mt][nt], (const uint32_t*)&AH[mt][kt], bh0, bh1);
                        mma16816(d1[mt][nt], (const uint32_t*)&AL[mt][kt], bh0, bh1);
                        mma16816(d1[mt][nt], (const uint32_t*)&AH[mt][kt], bl0, bl1);
                    }
                }
            }

            // ---- pack D1 pairs (adjacent channels) into A2 [m][kw] layout ----
#pragma unroll
            for (int nt = 0; nt < 4; nt++) {
                const int n0 = wid * 32 + nt * 8 + (lane & 3) * 2;
                const int cw = (n0 & 63) >> 1;     // k-pair word index
                const int tt = n0 >> 6;
#pragma unroll
                for (int mt = 0; mt < 2; mt++) {
                    const int gm = mt * 16 + (lane >> 2);
                    const float* dd = d1[mt][nt];
                    if (gm < V_) {
                        int m2 = tt * 25 + gm;
                        uint32_t h = packbf(dd[1], dd[0]);
                        float r0 = dd[0] - __uint_as_float(h << 16);
                        float r1 = dd[1] - __uint_as_float(h & 0xffff0000u);
                        a2h[m2 * 36 + cw] = h;
                        a2l[m2 * 36 + cw] = packbf(r1, r0);
                    }
                    if (gm + 8 < V_) {
                        int m2 = tt * 25 + gm + 8;
                        uint32_t h = packbf(dd[3], dd[2]);
                        float r0 = dd[2] - __uint_as_float(h << 16);
                        float r1 = dd[3] - __uint_as_float(h & 0xffff0000u);
                        a2h[m2 * 36 + cw] = h;
                        a2l[m2 * 36 + cw] = packbf(r1, r0);
                    }
                }
            }
        }
        __syncthreads();   // A2(s) ready; also guarantees GEMM2(s-1) reads done

        // ======== GEMM2: acc[m][o] += xa^T . W  (M=112,N=64,K=64), 4x2 ========
        // No trailing barrier: GEMM1(s+1) writes the OTHER A2 buffer, and the
        // barrier above (at s+1) orders buffer reuse at s+2.
        {
            const uint32_t abase_s = a2h0_u + ((s & 1) ? a2buf : 0u) + lds_lane_off;
            const uint4* wfs = g_Wf + (s * 4) * 8 * 32 + lane;
#pragma unroll
            for (int kt = 0; kt < 4; kt++) {
                uint4 Bf[4];
#pragma unroll
                for (int j = 0; j < 4; j++)
                    Bf[j] = __ldg(wfs + (kt * 8 + wx * 4 + j) * 32);

#pragma unroll
                for (int mti = 0; mti < 2; mti++) {
                    if (!(wy == 3 && mti == 1)) {   // rows 112..127 dead
                        const uint32_t abase =
                            abase_s + (uint32_t)((wy * 2 + mti) * 16 * 144 + kt * 32);
                        uint32_t ah[4], al[4];
                        ldsm_x4(ah, abase);
                        ldsm_x4(al, abase + a2dlt);
#pragma unroll
                        for (int j = 0; j < 4; j++) {
                            mma16816(acc[mti][j], ah, Bf[j].x, Bf[j].y);
                            mma16816(acc[mti][j], al, Bf[j].x, Bf[j].y);
                            mma16816(acc[mti][j], ah, Bf[j].z, Bf[j].w);
                        }
                    }
                }
            }
        }
    }

    // -------- Epilogue: BN applied per-thread, transpose via smem scratch ----
    // Scratch [o][m] stride 108 overlays xb (last read pre-barrier(s=2); any
    // warp writing here has passed barrier(s=2), laggards are in GEMM2(2)
    // which touches only A2/W). STS banks: 24*(lane&3)+m -> conflict-free.
    {
        float* scr = sm + SCR_O;
        const int nb = wx * 32 + (lane & 3) * 2;
        float alv[8], bsv[8];
#pragma unroll
        for (int j = 0; j < 4; j++) {
            alv[2 * j]     = ab[nb + j * 8];
            alv[2 * j + 1] = ab[nb + j * 8 + 1];
            bsv[2 * j]     = ab[64 + nb + j * 8];
            bsv[2 * j + 1] = ab[64 + nb + j * 8 + 1];
        }
#pragma unroll
        for (int mti = 0; mti < 2; mti++) {
            if (wy == 3 && mti == 1) continue;
#pragma unroll
            for (int half = 0; half < 2; half++) {
                int m = (wy * 2 + mti) * 16 + (lane >> 2) + half * 8;
                if (m < COLS) {
#pragma unroll
                    for (int j = 0; j < 4; j++) {
                        int o0 = nb + j * 8;
                        scr[o0 * 108 + m] =
                            fmaf(acc[mti][j][half * 2], alv[2 * j], bsv[2 * j]);
                        scr[(o0 + 1) * 108 + m] =
                            fmaf(acc[mti][j][half * 2 + 1], alv[2 * j + 1], bsv[2 * j + 1]);
                    }
                }
            }
        }
    }
    __syncthreads();

    // Coalesced residual-add + relu + store (float4 rows).
    {
        const float* scr = sm + SCR_O;
        const float4* xp = (const float4*)x;
        float4* op = (float4*)out;
        for (int i = tid; i < 1600; i += NTHREADS) {
            int o = i / 25;
            int q = i % 25;
            float4 r = __ldg(xp + ((n * 64 + o) * 1875 + bx * 25 + q));
            const float* sv = scr + o * 108 + 4 * q;
            float4 y;
            y.x = fmaxf(sv[0] + r.x, 0.0f);
            y.y = fmaxf(sv[1] + r.y, 0.0f);
            y.z = fmaxf(sv[2] + r.z, 0.0f);
            y.w = fmaxf(sv[3] + r.w, 0.0f);
            op[(n * 64 + o) * 1875 + bx * 25 + q] = y;
        }
    }
}

extern "C" void kernel_launch(void* const* d_in, const int* in_sizes, int n_in,
                              void* d_out, int out_size) {
    const float* x     = (const float*)d_in[0];
    const float* A     = (const float*)d_in[1];
    const float* PA1   = (const float*)d_in[2];
    const float* PA2   = (const float*)d_in[3];
    const float* Wc    = (const float*)d_in[4];
    const float* bc    = (const float*)d_in[5];
    const float* gamma = (const float*)d_in[6];
    const float* beta  = (const float*)d_in[7];
    const float* rmean = (const float*)d_in[8];
    const float* rvar  = (const float*)d_in[9];
    float* out = (float*)d_out;

    unit_gcn_prep<<<8, 256>>>(A, PA1, PA2, Wc, bc, gamma, beta, rmean, rvar);

    cudaFuncSetAttribute(unit_gcn_main,
                         cudaFuncAttributeMaxDynamicSharedMemorySize, SMEM_BYTES);
    dim3 grid(TBLK, N_);
    unit_gcn_main<<<grid, NTHREADS, SMEM_BYTES>>>(x, out);
}

// round 10
// speedup vs baseline: 1.0470x; 1.0470x over previous
#include <cuda_runtime.h>
#include <cuda_bf16.h>
#include <cstdint>

// Problem dims (fixed by the dataset)
#define N_   64
#define C_   64
#define T_   300
#define V_   25
#define S_   3
#define TT   4              // t positions per block
#define COLS 100            // TT*V_
#define TBLK 75             // T_/TT
#define NTHREADS 256

// xb row stride in 32-bit words. 265 (odd) -> staging STS.16 bank step
// 2*265 mod 32 = 18 (order 16): 2-way conflicts instead of 16-way at 264.
#define XBS  265

// -------- global folded parameters (written by prep kernel) --------
__device__ __align__(16) uint4 g_Wf[S_ * 4 * 8 * 32];   // W frags [s][kt][ntg][lane]
__device__ __align__(16) uint4 g_Af[S_ * 2 * 2 * 2 * 32]; // Ae^T frags [s][mt][kt][hl][lane]
__device__ __align__(16) float g_ab[128];                // alpha | bshift

// ---------------- bf16 / mma helpers ----------------
// packbf(hi_elem, lo_elem): low 16 bits = bf16(lo_elem)
__device__ __forceinline__ uint32_t packbf(float hi, float lo) {
    uint32_t d;
    asm("cvt.rn.bf16x2.f32 %0, %1, %2;" : "=r"(d) : "f"(hi), "f"(lo));
    return d;
}
__device__ __forceinline__ void mma16816(float* c, const uint32_t* a,
                                         uint32_t b0, uint32_t b1) {
    asm volatile(
        "mma.sync.aligned.m16n8k16.row.col.f32.bf16.bf16.f32 "
        "{%0,%1,%2,%3}, {%4,%5,%6,%7}, {%8,%9}, {%0,%1,%2,%3};"
        : "+f"(c[0]), "+f"(c[1]), "+f"(c[2]), "+f"(c[3])
        : "r"(a[0]), "r"(a[1]), "r"(a[2]), "r"(a[3]), "r"(b0), "r"(b1));
}
__device__ __forceinline__ void ldsm_x4(uint32_t* r, uint32_t addr) {
    asm volatile(
        "ldmatrix.sync.aligned.m8n8.x4.shared.b16 {%0,%1,%2,%3}, [%4];"
        : "=r"(r[0]), "=r"(r[1]), "=r"(r[2]), "=r"(r[3]) : "r"(addr));
}
__device__ __forceinline__ uint32_t smem_u32_of(const void* p) {
    uint32_t a;
    asm("{ .reg .u64 t; cvta.to.shared.u64 t, %1; cvt.u32.u64 %0, t; }"
        : "=r"(a) : "l"(p));
    return a;
}

// ---------------- prep: fold params (tiny, few blocks) ----------------
__global__ void unit_gcn_prep(const float* __restrict__ pA,
                              const float* __restrict__ pPA1,
                              const float* __restrict__ pPA2,
                              const float* __restrict__ pWc,
                              const float* __restrict__ pbc,
                              const float* __restrict__ pgamma,
                              const float* __restrict__ pbeta,
                              const float* __restrict__ prmean,
                              const float* __restrict__ prvar) {
    int tid = blockIdx.x * blockDim.x + threadIdx.x;

    // W fragments for GEMM2 B operand (col-major KxN), hi/lo bf16.
    for (int i = tid; i < S_ * 4 * 8 * 32; i += blockDim.x * gridDim.x) {
        int lane = i & 31;
        int ntg  = (i >> 5) & 7;
        int kt   = (i >> 8) & 3;
        int s    = i >> 10;
        int n  = ntg * 8 + (lane >> 2);
        int k0 = kt * 16 + (lane & 3) * 2;
        const float* wr = pWc + (s * 64 + n) * 64;
        float w0 = wr[k0], w1 = wr[k0 + 1], w8 = wr[k0 + 8], w9 = wr[k0 + 9];
        uint32_t h01 = packbf(w1, w0);
        uint32_t h89 = packbf(w9, w8);
        float r0 = w0 - __uint_as_float(h01 << 16);
        float r1 = w1 - __uint_as_float(h01 & 0xffff0000u);
        float r8 = w8 - __uint_as_float(h89 << 16);
        float r9 = w9 - __uint_as_float(h89 & 0xffff0000u);
        uint4 frag;
        frag.x = h01;
        frag.y = h89;
        frag.z = packbf(r1, r0);
        frag.w = packbf(r9, r8);
        g_Wf[i] = frag;
    }

    // Ae^T fragments for GEMM1 A operand (row-major 32x32, m=w, k=v), hi/lo.
    for (int i = tid; i < S_ * 2 * 2 * 2 * 32; i += blockDim.x * gridDim.x) {
        int lane = i & 31;
        int hl = (i >> 5) & 1;
        int kt = (i >> 6) & 1;
        int mt = (i >> 7) & 1;
        int s  = i >> 8;
        int gm = mt * 16 + (lane >> 2);
        int k0 = kt * 16 + (lane & 3) * 2;
        float e[8];
        int ms[2] = {gm, gm + 8};
        int ks[4] = {k0, k0 + 1, k0 + 8, k0 + 9};
#pragma unroll
        for (int kk = 0; kk < 4; kk++)
#pragma unroll
            for (int mm = 0; mm < 2; mm++) {
                int m = ms[mm], k = ks[kk];
                float v = 0.0f;
                if (m < V_ && k < V_) {
                    int idx = (s * V_ + k) * V_ + m;
                    v = pA[idx] * pPA1[idx] + pPA2[idx];
                }
                e[kk * 2 + mm] = v;
            }
        if (hl) {
#pragma unroll
            for (int q = 0; q < 8; q++) {
                float h = __bfloat162float(__float2bfloat16(e[q]));
                e[q] = e[q] - h;
            }
        }
        uint4 frag;
        frag.x = packbf(e[2], e[0]);
        frag.y = packbf(e[3], e[1]);
        frag.z = packbf(e[6], e[4]);
        frag.w = packbf(e[7], e[5]);
        g_Af[i] = frag;
    }

    // BN fold: out = gemm*alpha + bshift (+x, relu). Bias folded into bshift.
    if (tid < C_) {
        float sc = pgamma[tid] / sqrtf(prvar[tid] + 1e-5f);
        float btot = pbc[tid] + pbc[64 + tid] + pbc[128 + tid];
        g_ab[tid] = sc;
        g_ab[64 + tid] = btot * sc + (pbeta[tid] - prmean[tid] * sc);
    }
}

// ---------------- main fused kernel ----------------
// smem layout (float index). A2 layout: [m][kw], 36-word rows (144B) for
// conflict-free ldmatrix and pack-stores. xb rows padded to XBS=265.
#define AB_O   0                      // 128: alpha|bshift
#define A2H_O  128                    // 112 x 36 = 4032 (GEMM2 A hi, bf16x2 words)
#define A2L_O  4160                   // 4032 (lo)
#define XBH_O  8192                   // 16 x 265 = 4240 (GEMM1 B hi)
#define XBL_O  12432                  // 4240 (lo)
#define SMEM_FLOATS 16672
#define SMEM_BYTES  (SMEM_FLOATS * 4) // 66688 -> 2 CTAs/SM

__global__ void __launch_bounds__(NTHREADS, 2)
unit_gcn_main(const float* __restrict__ x, float* __restrict__ out) {
    const int n  = blockIdx.y;
    const int bx = blockIdx.x;       // t-tile
    const int t0 = bx * TT;
    const int tid = threadIdx.x;
    const int wid = tid >> 5;
    const int lane = tid & 31;

    extern __shared__ float sm[];
    float* ab = sm + AB_O;
    uint32_t* a2h = (uint32_t*)(sm + A2H_O);
    uint32_t* a2l = (uint32_t*)(sm + A2L_O);
    uint32_t* xbh = (uint32_t*)(sm + XBH_O);
    uint32_t* xbl = (uint32_t*)(sm + XBL_O);

    // Stage BN constants
    if (tid < 128) ab[tid] = g_ab[tid];

    // Zero xb pad rows 12..15 (v >= 25 region; v=24 lands in row 12 half 0)
    for (int i = tid; i < 4 * XBS; i += NTHREADS) {
        xbh[12 * XBS + i] = 0u;
        xbl[12 * XBS + i] = 0u;
    }
    __syncthreads();   // pad-zero must precede staging writes into row 12

    // Stage x tile as k-packed bf16 hi/lo for GEMM1 B.
    {
        const float4* xp = (const float4*)x;
        __nv_bfloat16* bh = (__nv_bfloat16*)xbh;
        __nv_bfloat16* bl = (__nv_bfloat16*)xbl;
        for (int q = tid; q < 1600; q += NTHREADS) {
            int c = q / 25;
            int f = q % 25;
            float4 val = xp[(n * 64 + c) * 1875 + bx * 25 + f];
            int p0 = f * 4;
            float vv[4] = {val.x, val.y, val.z, val.w};
#pragma unroll
            for (int j = 0; j < 4; j++) {
                int p = p0 + j;
                int tt = p / 25;
                int w = p - tt * 25;        // joint index v
                float v = vv[j];
                __nv_bfloat16 h = __float2bfloat16(v);
                __nv_bfloat16 l = __float2bfloat16(v - __bfloat162float(h));
                int half = ((w >> 1) * XBS + tt * 64 + c) * 2 + (w & 1);
                bh[half] = h;
                bl[half] = l;
            }
        }
    }
    __syncthreads();

    // GEMM2 warp coords: wy -> m rows, wx -> n channels
    const int wy = wid & 3;
    const int wx = wid >> 2;

    float acc[2][4][4];
#pragma unroll
    for (int i = 0; i < 2; i++)
#pragma unroll
        for (int j = 0; j < 4; j++)
#pragma unroll
            for (int q = 0; q < 4; q++) acc[i][j][q] = 0.0f;

    // ldmatrix lane addressing (A2 base in u32 shared space)
    const uint32_t a2h_u = smem_u32_of(a2h);
    const uint32_t a2dlt = (uint32_t)((A2L_O - A2H_O) * 4);
    const uint32_t lds_lane_off = (uint32_t)((lane & 15) * 144 + (lane >> 4) * 16);

#pragma unroll
    for (int s = 0; s < S_; s++) {
        // ======== GEMM1: D1[w, tt*64+c] = Ae^T . xs  (M=32,N=256,K=32) ========
        // warp owns n-slice [wid*32, wid*32+32)
        {
            uint4 AH[2][2], AL[2][2];
#pragma unroll
            for (int mt = 0; mt < 2; mt++)
#pragma unroll
                for (int kt = 0; kt < 2; kt++) {
                    AH[mt][kt] = __ldg(g_Af + ((((s * 2 + mt) * 2 + kt) * 2 + 0) * 32) + lane);
                    AL[mt][kt] = __ldg(g_Af + ((((s * 2 + mt) * 2 + kt) * 2 + 1) * 32) + lane);
                }

            float d1[2][4][4];
#pragma unroll
            for (int i = 0; i < 2; i++)
#pragma unroll
                for (int j = 0; j < 4; j++)
#pragma unroll
                    for (int q = 0; q < 4; q++) d1[i][j][q] = 0.0f;

#pragma unroll
            for (int kt = 0; kt < 2; kt++) {
                const int rb = kt * 8 + (lane & 3);
#pragma unroll
                for (int nt = 0; nt < 4; nt++) {
                    const int nn = wid * 32 + nt * 8 + (lane >> 2);
                    uint32_t bh0 = xbh[rb * XBS + nn];
                    uint32_t bh1 = xbh[(rb + 4) * XBS + nn];
                    uint32_t bl0 = xbl[rb * XBS + nn];
                    uint32_t bl1 = xbl[(rb + 4) * XBS + nn];
#pragma unroll
                    for (int mt = 0; mt < 2; mt++) {
                        mma16816(d1[mt][nt], (const uint32_t*)&AH[mt][kt], bh0, bh1);
                        mma16816(d1[mt][nt], (const uint32_t*)&AL[mt][kt], bh0, bh1);
                        mma16816(d1[mt][nt], (const uint32_t*)&AH[mt][kt], bl0, bl1);
                    }
                }
            }

            // ---- pack D1 pairs (adjacent channels) into A2 [m][kw] layout ----
#pragma unroll
            for (int nt = 0; nt < 4; nt++) {
                const int n0 = wid * 32 + nt * 8 + (lane & 3) * 2;
                const int cw = (n0 & 63) >> 1;     // k-pair word index
                const int tt = n0 >> 6;
#pragma unroll
                for (int mt = 0; mt < 2; mt++) {
                    const int gm = mt * 16 + (lane >> 2);
                    const float* dd = d1[mt][nt];
                    if (gm < V_) {
                        int m2 = tt * 25 + gm;
                        uint32_t h = packbf(dd[1], dd[0]);
                        float r0 = dd[0] - __uint_as_float(h << 16);
                        float r1 = dd[1] - __uint_as_float(h & 0xffff0000u);
                        a2h[m2 * 36 + cw] = h;
                        a2l[m2 * 36 + cw] = packbf(r1, r0);
                    }
                    if (gm + 8 < V_) {
                        int m2 = tt * 25 + gm + 8;
                        uint32_t h = packbf(dd[3], dd[2]);
                        float r0 = dd[2] - __uint_as_float(h << 16);
                        float r1 = dd[3] - __uint_as_float(h & 0xffff0000u);
                        a2h[m2 * 36 + cw] = h;
                        a2l[m2 * 36 + cw] = packbf(r1, r0);
                    }
                }
            }
        }
        __syncthreads();   // A2 tiles ready

        // ======== GEMM2: acc[m][o] += xa^T . W  (M=112,N=64,K=64), 4x2 ========
        {
            const uint4* wfs = g_Wf + (s * 4) * 8 * 32 + lane;
#pragma unroll
            for (int kt = 0; kt < 4; kt++) {
                uint4 Bf[4];
#pragma unroll
                for (int j = 0; j < 4; j++)
                    Bf[j] = __ldg(wfs + (kt * 8 + wx * 4 + j) * 32);

#pragma unroll
                for (int mti = 0; mti < 2; mti++) {
                    if (!(wy == 3 && mti == 1)) {   // rows 112..127 dead
                        const uint32_t abase =
                            a2h_u + (uint32_t)((wy * 2 + mti) * 16 * 144 + kt * 32)
                            + lds_lane_off;
                        uint32_t ah[4], al[4];
                        ldsm_x4(ah, abase);
                        ldsm_x4(al, abase + a2dlt);
#pragma unroll
                        for (int j = 0; j < 4; j++) {
                            mma16816(acc[mti][j], ah, Bf[j].x, Bf[j].y);
                            mma16816(acc[mti][j], al, Bf[j].x, Bf[j].y);
                            mma16816(acc[mti][j], ah, Bf[j].z, Bf[j].w);
                        }
                    }
                }
            }
        }
        if (s < S_ - 1) __syncthreads();   // before next s overwrites A2
    }

    // -------- Epilogue: BN + residual(from gmem, L2-hot) + relu, store ------
    const int nb = wx * 32 + (lane & 3) * 2;
    float alv[8], bsv[8];
#pragma unroll
    for (int j = 0; j < 4; j++) {
        alv[2 * j]     = ab[nb + j * 8];
        alv[2 * j + 1] = ab[nb + j * 8 + 1];
        bsv[2 * j]     = ab[64 + nb + j * 8];
        bsv[2 * j + 1] = ab[64 + nb + j * 8 + 1];
    }

#pragma unroll
    for (int mti = 0; mti < 2; mti++) {
#pragma unroll
        for (int half = 0; half < 2; half++) {
            int m = (wy * 2 + mti) * 16 + (lane >> 2) + half * 8;
            if (m < COLS) {
                int tt = m / 25;
                int w  = m - tt * 25;
                int base = n * 480000 + (t0 + tt) * 25 + w;
#pragma unroll
                for (int j = 0; j < 4; j++) {
                    int o0 = nb + j * 8;
                    float c0 = acc[mti][j][half * 2];
                    float c1 = acc[mti][j][half * 2 + 1];
                    float r0 = __ldg(x + base + o0 * 7500);
                    float r1 = __ldg(x + base + (o0 + 1) * 7500);
                    float y0 = fmaf(c0, alv[2 * j], bsv[2 * j]) + r0;
                    float y1 = fmaf(c1, alv[2 * j + 1], bsv[2 * j + 1]) + r1;
                    out[base + o0 * 7500]       = fmaxf(y0, 0.0f);
                    out[base + (o0 + 1) * 7500] = fmaxf(y1, 0.0f);
                }
            }
        }
    }
}

extern "C" void kernel_launch(void* const* d_in, const int* in_sizes, int n_in,
                              void* d_out, int out_size) {
    const float* x     = (const float*)d_in[0];
    const float* A     = (const float*)d_in[1];
    const float* PA1   = (const float*)d_in[2];
    const float* PA2   = (const float*)d_in[3];
    const float* Wc    = (const float*)d_in[4];
    const float* bc    = (const float*)d_in[5];
    const float* gamma = (const float*)d_in[6];
    const float* beta  = (const float*)d_in[7];
    const float* rmean = (const float*)d_in[8];
    const float* rvar  = (const float*)d_in[9];
    float* out = (float*)d_out;

    unit_gcn_prep<<<8, 256>>>(A, PA1, PA2, Wc, bc, gamma, beta, rmean, rvar);

    cudaFuncSetAttribute(unit_gcn_main,
                         cudaFuncAttributeMaxDynamicSharedMemorySize, SMEM_BYTES);
    dim3 grid(TBLK, N_);
    unit_gcn_main<<<grid, NTHREADS, SMEM_BYTES>>>(x, out);
}

// round 11
// speedup vs baseline: 1.0691x; 1.0212x over previous
#include <cuda_runtime.h>
#include <cuda_bf16.h>
#include <cstdint>

// Problem dims (fixed by the dataset)
#define N_   64
#define C_   64
#define T_   300
#define V_   25
#define S_   3
#define TT   4              // t positions per block
#define COLS 100            // TT*V_
#define TBLK 75             // T_/TT
#define NTHREADS 256

// xb row stride in 32-bit words (odd -> staging STS.16 2-way instead of 16-way)
#define XBS  265

// -------- global folded parameters (written by prep kernel) --------
__device__ __align__(16) uint4 g_Wf[S_ * 4 * 8 * 32];   // W frags [s][kt][ntg][lane]
__device__ __align__(16) uint4 g_Af[S_ * 2 * 2 * 2 * 32]; // Ae^T frags [s][mt][kt][hl][lane]
__device__ __align__(16) float g_ab[128];                // alpha | bshift

// ---------------- bf16 / mma helpers ----------------
// packbf(hi_elem, lo_elem): low 16 bits = bf16(lo_elem)
__device__ __forceinline__ uint32_t packbf(float hi, float lo) {
    uint32_t d;
    asm("cvt.rn.bf16x2.f32 %0, %1, %2;" : "=r"(d) : "f"(hi), "f"(lo));
    return d;
}
__device__ __forceinline__ void mma16816(float* c, const uint32_t* a,
                                         uint32_t b0, uint32_t b1) {
    asm volatile(
        "mma.sync.aligned.m16n8k16.row.col.f32.bf16.bf16.f32 "
        "{%0,%1,%2,%3}, {%4,%5,%6,%7}, {%8,%9}, {%0,%1,%2,%3};"
        : "+f"(c[0]), "+f"(c[1]), "+f"(c[2]), "+f"(c[3])
        : "r"(a[0]), "r"(a[1]), "r"(a[2]), "r"(a[3]), "r"(b0), "r"(b1));
}
__device__ __forceinline__ void ldsm_x4(uint32_t* r, uint32_t addr) {
    asm volatile(
        "ldmatrix.sync.aligned.m8n8.x4.shared.b16 {%0,%1,%2,%3}, [%4];"
        : "=r"(r[0]), "=r"(r[1]), "=r"(r[2]), "=r"(r[3]) : "r"(addr));
}
__device__ __forceinline__ uint32_t smem_u32_of(const void* p) {
    uint32_t a;
    asm("{ .reg .u64 t; cvta.to.shared.u64 t, %1; cvt.u32.u64 %0, t; }"
        : "=r"(a) : "l"(p));
    return a;
}

// ---------------- prep: fold params (tiny, few blocks) ----------------
__global__ void unit_gcn_prep(const float* __restrict__ pA,
                              const float* __restrict__ pPA1,
                              const float* __restrict__ pPA2,
                              const float* __restrict__ pWc,
                              const float* __restrict__ pbc,
                              const float* __restrict__ pgamma,
                              const float* __restrict__ pbeta,
                              const float* __restrict__ prmean,
                              const float* __restrict__ prvar) {
    int tid = blockIdx.x * blockDim.x + threadIdx.x;

    // W fragments for GEMM2 B operand (col-major KxN), hi/lo bf16.
    for (int i = tid; i < S_ * 4 * 8 * 32; i += blockDim.x * gridDim.x) {
        int lane = i & 31;
        int ntg  = (i >> 5) & 7;
        int kt   = (i >> 8) & 3;
        int s    = i >> 10;
        int n  = ntg * 8 + (lane >> 2);
        int k0 = kt * 16 + (lane & 3) * 2;
        const float* wr = pWc + (s * 64 + n) * 64;
        float w0 = wr[k0], w1 = wr[k0 + 1], w8 = wr[k0 + 8], w9 = wr[k0 + 9];
        uint32_t h01 = packbf(w1, w0);
        uint32_t h89 = packbf(w9, w8);
        float r0 = w0 - __uint_as_float(h01 << 16);
        float r1 = w1 - __uint_as_float(h01 & 0xffff0000u);
        float r8 = w8 - __uint_as_float(h89 << 16);
        float r9 = w9 - __uint_as_float(h89 & 0xffff0000u);
        uint4 frag;
        frag.x = h01;
        frag.y = h89;
        frag.z = packbf(r1, r0);
        frag.w = packbf(r9, r8);
        g_Wf[i] = frag;
    }

    // Ae^T fragments for GEMM1 A operand (row-major 32x32, m=w, k=v), hi/lo.
    for (int i = tid; i < S_ * 2 * 2 * 2 * 32; i += blockDim.x * gridDim.x) {
        int lane = i & 31;
        int hl = (i >> 5) & 1;
        int kt = (i >> 6) & 1;
        int mt = (i >> 7) & 1;
        int s  = i >> 8;
        int gm = mt * 16 + (lane >> 2);
        int k0 = kt * 16 + (lane & 3) * 2;
        float e[8];
        int ms[2] = {gm, gm + 8};
        int ks[4] = {k0, k0 + 1, k0 + 8, k0 + 9};
#pragma unroll
        for (int kk = 0; kk < 4; kk++)
#pragma unroll
            for (int mm = 0; mm < 2; mm++) {
                int m = ms[mm], k = ks[kk];
                float v = 0.0f;
                if (m < V_ && k < V_) {
                    int idx = (s * V_ + k) * V_ + m;
                    v = pA[idx] * pPA1[idx] + pPA2[idx];
                }
                e[kk * 2 + mm] = v;
            }
        if (hl) {
#pragma unroll
            for (int q = 0; q < 8; q++) {
                float h = __bfloat162float(__float2bfloat16(e[q]));
                e[q] = e[q] - h;
            }
        }
        uint4 frag;
        frag.x = packbf(e[2], e[0]);
        frag.y = packbf(e[3], e[1]);
        frag.z = packbf(e[6], e[4]);
        frag.w = packbf(e[7], e[5]);
        g_Af[i] = frag;
    }

    // BN fold: out = gemm*alpha + bshift (+x, relu). Bias folded into bshift.
    if (tid < C_) {
        float sc = pgamma[tid] / sqrtf(prvar[tid] + 1e-5f);
        float btot = pbc[tid] + pbc[64 + tid] + pbc[128 + tid];
        g_ab[tid] = sc;
        g_ab[64 + tid] = btot * sc + (pbeta[tid] - prmean[tid] * sc);
    }
}

// ---------------- main fused kernel ----------------
// smem layout (float index). A2 double-buffered: [m][kw], 36-word rows.
#define AB_O    0                     // 128: alpha|bshift
#define A2H0_O  128                   // 4032
#define A2L0_O  4160                  // 4032
#define A2H1_O  8192                  // 4032
#define A2L1_O  12224                 // 4032
#define XBH_O   16256                 // 16 x 265 = 4240
#define XBL_O   20496                 // 4240
#define SMEM_FLOATS 24736
#define SMEM_BYTES  (SMEM_FLOATS * 4) // 98944 -> 2 CTAs/SM

struct G1Ctx {
    uint32_t* xbh;
    uint32_t* xbl;
    int wid, lane;
};

// GEMM1 for subset s, writing A2 buffer (a2h/a2l). Packs per-nt to cap regs.
__device__ __forceinline__ void gemm1_subset(const G1Ctx& g, int s,
                                             uint32_t* a2h, uint32_t* a2l) {
    const int wid = g.wid, lane = g.lane;
    uint4 AH[2][2], AL[2][2];
#pragma unroll
    for (int mt = 0; mt < 2; mt++)
#pragma unroll
        for (int kt = 0; kt < 2; kt++) {
            AH[mt][kt] = __ldg(g_Af + ((((s * 2 + mt) * 2 + kt) * 2 + 0) * 32) + lane);
            AL[mt][kt] = __ldg(g_Af + ((((s * 2 + mt) * 2 + kt) * 2 + 1) * 32) + lane);
        }

#pragma unroll
    for (int nt = 0; nt < 4; nt++) {
        float d1[2][4];
#pragma unroll
        for (int i = 0; i < 2; i++)
#pragma unroll
            for (int q = 0; q < 4; q++) d1[i][q] = 0.0f;

        const int nn = wid * 32 + nt * 8 + (lane >> 2);
#pragma unroll
        for (int kt = 0; kt < 2; kt++) {
            const int rb = kt * 8 + (lane & 3);
            uint32_t bh0 = g.xbh[rb * XBS + nn];
            uint32_t bh1 = g.xbh[(rb + 4) * XBS + nn];
            uint32_t bl0 = g.xbl[rb * XBS + nn];
            uint32_t bl1 = g.xbl[(rb + 4) * XBS + nn];
#pragma unroll
            for (int mt = 0; mt < 2; mt++) {
                mma16816(d1[mt], (const uint32_t*)&AH[mt][kt], bh0, bh1);
                mma16816(d1[mt], (const uint32_t*)&AL[mt][kt], bh0, bh1);
                mma16816(d1[mt], (const uint32_t*)&AH[mt][kt], bl0, bl1);
            }
        }

        // pack this nt slice into A2 [m][kw]
        const int n0 = wid * 32 + nt * 8 + (lane & 3) * 2;
        const int cw = (n0 & 63) >> 1;
        const int tt = n0 >> 6;
#pragma unroll
        for (int mt = 0; mt < 2; mt++) {
            const int gm = mt * 16 + (lane >> 2);
            const float* dd = d1[mt];
            if (gm < V_) {
                int m2 = tt * 25 + gm;
                uint32_t h = packbf(dd[1], dd[0]);
                float r0 = dd[0] - __uint_as_float(h << 16);
                float r1 = dd[1] - __uint_as_float(h & 0xffff0000u);
                a2h[m2 * 36 + cw] = h;
                a2l[m2 * 36 + cw] = packbf(r1, r0);
            }
            if (gm + 8 < V_) {
                int m2 = tt * 25 + gm + 8;
                uint32_t h = packbf(dd[3], dd[2]);
                float r0 = dd[2] - __uint_as_float(h << 16);
                float r1 = dd[3] - __uint_as_float(h & 0xffff0000u);
                a2h[m2 * 36 + cw] = h;
                a2l[m2 * 36 + cw] = packbf(r1, r0);
            }
        }
    }
}

// GEMM2 for subset s reading A2 buffer at byte base abase_s (hi; +a2dlt = lo).
__device__ __forceinline__ void gemm2_subset(float acc[2][4][4], int s,
                                             uint32_t abase_s, uint32_t a2dlt,
                                             int wy, int wx, int lane) {
    const uint4* wfs = g_Wf + (s * 4) * 8 * 32 + lane;
#pragma unroll
    for (int kt = 0; kt < 4; kt++) {
        uint4 Bf[4];
#pragma unroll
        for (int j = 0; j < 4; j++)
            Bf[j] = __ldg(wfs + (kt * 8 + wx * 4 + j) * 32);

#pragma unroll
        for (int mti = 0; mti < 2; mti++) {
            if (!(wy == 3 && mti == 1)) {   // rows 112..127 dead
                const uint32_t abase =
                    abase_s + (uint32_t)((wy * 2 + mti) * 16 * 144 + kt * 32);
                uint32_t ah[4], al[4];
                ldsm_x4(ah, abase);
                ldsm_x4(al, abase + a2dlt);
#pragma unroll
                for (int j = 0; j < 4; j++) {
                    mma16816(acc[mti][j], ah, Bf[j].x, Bf[j].y);
                    mma16816(acc[mti][j], al, Bf[j].x, Bf[j].y);
                    mma16816(acc[mti][j], ah, Bf[j].z, Bf[j].w);
                }
            }
        }
    }
}

__global__ void __launch_bounds__(NTHREADS, 2)
unit_gcn_main(const float* __restrict__ x, float* __restrict__ out) {
    const int n  = blockIdx.y;
    const int bx = blockIdx.x;       // t-tile
    const int t0 = bx * TT;
    const int tid = threadIdx.x;
    const int wid = tid >> 5;
    const int lane = tid & 31;

    extern __shared__ float sm[];
    float* ab = sm + AB_O;
    uint32_t* xbh = (uint32_t*)(sm + XBH_O);
    uint32_t* xbl = (uint32_t*)(sm + XBL_O);

    // Stage BN constants
    if (tid < 128) ab[tid] = g_ab[tid];

    // Zero xb pad rows 12..15
    for (int i = tid; i < 4 * XBS; i += NTHREADS) {
        xbh[12 * XBS + i] = 0u;
        xbl[12 * XBS + i] = 0u;
    }
    __syncthreads();

    // Stage x tile as k-packed bf16 hi/lo for GEMM1 B.
    {
        const float4* xp = (const float4*)x;
        __nv_bfloat16* bh = (__nv_bfloat16*)xbh;
        __nv_bfloat16* bl = (__nv_bfloat16*)xbl;
        for (int q = tid; q < 1600; q += NTHREADS) {
            int c = q / 25;
            int f = q % 25;
            float4 val = xp[(n * 64 + c) * 1875 + bx * 25 + f];
            int p0 = f * 4;
            float vv[4] = {val.x, val.y, val.z, val.w};
#pragma unroll
            for (int j = 0; j < 4; j++) {
                int p = p0 + j;
                int tt = p / 25;
                int w = p - tt * 25;
                float v = vv[j];
                __nv_bfloat16 h = __float2bfloat16(v);
                __nv_bfloat16 l = __float2bfloat16(v - __bfloat162float(h));
                int half = ((w >> 1) * XBS + tt * 64 + c) * 2 + (w & 1);
                bh[half] = h;
                bl[half] = l;
            }
        }
    }
    __syncthreads();

    const int wy = wid & 3;
    const int wx = wid >> 2;

    float acc[2][4][4];
#pragma unroll
    for (int i = 0; i < 2; i++)
#pragma unroll
        for (int j = 0; j < 4; j++)
#pragma unroll
            for (int q = 0; q < 4; q++) acc[i][j][q] = 0.0f;

    const uint32_t a2h0_u = smem_u32_of(sm + A2H0_O);
    const uint32_t a2dlt = (uint32_t)((A2L0_O - A2H0_O) * 4);
    const uint32_t a2buf = (uint32_t)((A2H1_O - A2H0_O) * 4);
    const uint32_t lds_lane_off = (uint32_t)((lane & 15) * 144 + (lane >> 4) * 16);

    G1Ctx g;
    g.xbh = xbh; g.xbl = xbl; g.wid = wid; g.lane = lane;
    uint32_t* a2h_b[2] = {(uint32_t*)(sm + A2H0_O), (uint32_t*)(sm + A2H1_O)};
    uint32_t* a2l_b[2] = {(uint32_t*)(sm + A2L0_O), (uint32_t*)(sm + A2L1_O)};

    // ---- software pipeline over subsets ----
    gemm1_subset(g, 0, a2h_b[0], a2l_b[0]);
    __syncthreads();                                   // A2(0) ready
#pragma unroll
    for (int s = 0; s < S_; s++) {
        if (s < S_ - 1)
            gemm1_subset(g, s + 1, a2h_b[(s + 1) & 1], a2l_b[(s + 1) & 1]);
        gemm2_subset(acc, s,
                     a2h0_u + ((s & 1) ? a2buf : 0u) + lds_lane_off,
                     a2dlt, wy, wx, lane);
        if (s < S_ - 1) __syncthreads();               // A2(s+1) ready; G2(s) reads done
    }

    // -------- Epilogue: BN + residual(from gmem, L2-hot) + relu, store ------
    const int nb = wx * 32 + (lane & 3) * 2;
    float alv[8], bsv[8];
#pragma unroll
    for (int j = 0; j < 4; j++) {
        alv[2 * j]     = ab[nb + j * 8];
        alv[2 * j + 1] = ab[nb + j * 8 + 1];
        bsv[2 * j]     = ab[64 + nb + j * 8];
        bsv[2 * j + 1] = ab[64 + nb + j * 8 + 1];
    }

#pragma unroll
    for (int mti = 0; mti < 2; mti++) {
#pragma unroll
        for (int half = 0; half < 2; half++) {
            int m = (wy * 2 + mti) * 16 + (lane >> 2) + half * 8;
            if (m < COLS) {
                int tt = m / 25;
                int w  = m - tt * 25;
                int base = n * 480000 + (t0 + tt) * 25 + w;
#pragma unroll
                for (int j = 0; j < 4; j++) {
                    int o0 = nb + j * 8;
                    float c0 = acc[mti][j][half * 2];
                    float c1 = acc[mti][j][half * 2 + 1];
                    float r0 = __ldg(x + base + o0 * 7500);
                    float r1 = __ldg(x + base + (o0 + 1) * 7500);
                    float y0 = fmaf(c0, alv[2 * j], bsv[2 * j]) + r0;
                    float y1 = fmaf(c1, alv[2 * j + 1], bsv[2 * j + 1]) + r1;
                    out[base + o0 * 7500]       = fmaxf(y0, 0.0f);
                    out[base + (o0 + 1) * 7500] = fmaxf(y1, 0.0f);
                }
            }
        }
    }
}

extern "C" void kernel_launch(void* const* d_in, const int* in_sizes, int n_in,
                              void* d_out, int out_size) {
    const float* x     = (const float*)d_in[0];
    const float* A     = (const float*)d_in[1];
    const float* PA1   = (const float*)d_in[2];
    const float* PA2   = (const float*)d_in[3];
    const float* Wc    = (const float*)d_in[4];
    const float* bc    = (const float*)d_in[5];
    const float* gamma = (const float*)d_in[6];
    const float* beta  = (const float*)d_in[7];
    const float* rmean = (const float*)d_in[8];
    const float* rvar  = (const float*)d_in[9];
    float* out = (float*)d_out;

    unit_gcn_prep<<<8, 256>>>(A, PA1, PA2, Wc, bc, gamma, beta, rmean, rvar);

    cudaFuncSetAttribute(unit_gcn_main,
                         cudaFuncAttributeMaxDynamicSharedMemorySize, SMEM_BYTES);
    dim3 grid(TBLK, N_);
    unit_gcn_main<<<grid, NTHREADS, SMEM_BYTES>>>(x, out);
}

// round 12
// speedup vs baseline: 1.1758x; 1.0998x over previous
#include <cuda_runtime.h>
#include <cuda_bf16.h>
#include <cstdint>

// Problem dims (fixed by the dataset)
#define N_   64
#define C_   64
#define T_   300
#define V_   25
#define S_   3
#define TT   4              // t positions per block
#define COLS 100            // TT*V_
#define TBLK 75             // T_/TT
#define NTHREADS 256

// xb row stride in 32-bit words (odd -> conflict-free word stores, step 9)
#define XBS  265

// -------- global folded parameters (written by prep kernel) --------
__device__ __align__(16) uint4 g_Wf[S_ * 4 * 8 * 32];   // W frags [s][kt][ntg][lane]
__device__ __align__(16) uint4 g_Af[S_ * 2 * 2 * 2 * 32]; // Ae^T frags [s][mt][kt][hl][lane]
__device__ __align__(16) float g_ab[128];                // alpha | bshift

// ---------------- bf16 / mma helpers ----------------
// packbf(hi_elem, lo_elem): low 16 bits = bf16(lo_elem)
__device__ __forceinline__ uint32_t packbf(float hi, float lo) {
    uint32_t d;
    asm("cvt.rn.bf16x2.f32 %0, %1, %2;" : "=r"(d) : "f"(hi), "f"(lo));
    return d;
}
__device__ __forceinline__ void mma16816(float* c, const uint32_t* a,
                                         uint32_t b0, uint32_t b1) {
    asm volatile(
        "mma.sync.aligned.m16n8k16.row.col.f32.bf16.bf16.f32 "
        "{%0,%1,%2,%3}, {%4,%5,%6,%7}, {%8,%9}, {%0,%1,%2,%3};"
        : "+f"(c[0]), "+f"(c[1]), "+f"(c[2]), "+f"(c[3])
        : "r"(a[0]), "r"(a[1]), "r"(a[2]), "r"(a[3]), "r"(b0), "r"(b1));
}
__device__ __forceinline__ void ldsm_x4(uint32_t* r, uint32_t addr) {
    asm volatile(
        "ldmatrix.sync.aligned.m8n8.x4.shared.b16 {%0,%1,%2,%3}, [%4];"
        : "=r"(r[0]), "=r"(r[1]), "=r"(r[2]), "=r"(r[3]) : "r"(addr));
}
__device__ __forceinline__ uint32_t smem_u32_of(const void* p) {
    uint32_t a;
    asm("{ .reg .u64 t; cvta.to.shared.u64 t, %1; cvt.u32.u64 %0, t; }"
        : "=r"(a) : "l"(p));
    return a;
}

// ---------------- prep: fold params (tiny, few blocks) ----------------
__global__ void unit_gcn_prep(const float* __restrict__ pA,
                              const float* __restrict__ pPA1,
                              const float* __restrict__ pPA2,
                              const float* __restrict__ pWc,
                              const float* __restrict__ pbc,
                              const float* __restrict__ pgamma,
                              const float* __restrict__ pbeta,
                              const float* __restrict__ prmean,
                              const float* __restrict__ prvar) {
    int tid = blockIdx.x * blockDim.x + threadIdx.x;

    // W fragments for GEMM2 B operand (col-major KxN), hi/lo bf16.
    for (int i = tid; i < S_ * 4 * 8 * 32; i += blockDim.x * gridDim.x) {
        int lane = i & 31;
        int ntg  = (i >> 5) & 7;
        int kt   = (i >> 8) & 3;
        int s    = i >> 10;
        int n  = ntg * 8 + (lane >> 2);
        int k0 = kt * 16 + (lane & 3) * 2;
        const float* wr = pWc + (s * 64 + n) * 64;
        float w0 = wr[k0], w1 = wr[k0 + 1], w8 = wr[k0 + 8], w9 = wr[k0 + 9];
        uint32_t h01 = packbf(w1, w0);
        uint32_t h89 = packbf(w9, w8);
        float r0 = w0 - __uint_as_float(h01 << 16);
        float r1 = w1 - __uint_as_float(h01 & 0xffff0000u);
        float r8 = w8 - __uint_as_float(h89 << 16);
        float r9 = w9 - __uint_as_float(h89 & 0xffff0000u);
        uint4 frag;
        frag.x = h01;
        frag.y = h89;
        frag.z = packbf(r1, r0);
        frag.w = packbf(r9, r8);
        g_Wf[i] = frag;
    }

    // Ae^T fragments for GEMM1 A operand (row-major 32x32, m=w, k=v), hi/lo.
    for (int i = tid; i < S_ * 2 * 2 * 2 * 32; i += blockDim.x * gridDim.x) {
        int lane = i & 31;
        int hl = (i >> 5) & 1;
        int kt = (i >> 6) & 1;
        int mt = (i >> 7) & 1;
        int s  = i >> 8;
        int gm = mt * 16 + (lane >> 2);
        int k0 = kt * 16 + (lane & 3) * 2;
        float e[8];
        int ms[2] = {gm, gm + 8};
        int ks[4] = {k0, k0 + 1, k0 + 8, k0 + 9};
#pragma unroll
        for (int kk = 0; kk < 4; kk++)
#pragma unroll
            for (int mm = 0; mm < 2; mm++) {
                int m = ms[mm], k = ks[kk];
                float v = 0.0f;
                if (m < V_ && k < V_) {
                    int idx = (s * V_ + k) * V_ + m;
                    v = pA[idx] * pPA1[idx] + pPA2[idx];
                }
                e[kk * 2 + mm] = v;
            }
        if (hl) {
#pragma unroll
            for (int q = 0; q < 8; q++) {
                float h = __bfloat162float(__float2bfloat16(e[q]));
                e[q] = e[q] - h;
            }
        }
        uint4 frag;
        frag.x = packbf(e[2], e[0]);
        frag.y = packbf(e[3], e[1]);
        frag.z = packbf(e[6], e[4]);
        frag.w = packbf(e[7], e[5]);
        g_Af[i] = frag;
    }

    // BN fold: out = gemm*alpha + bshift (+x, relu). Bias folded into bshift.
    if (tid < C_) {
        float sc = pgamma[tid] / sqrtf(prvar[tid] + 1e-5f);
        float btot = pbc[tid] + pbc[64 + tid] + pbc[128 + tid];
        g_ab[tid] = sc;
        g_ab[64 + tid] = btot * sc + (pbeta[tid] - prmean[tid] * sc);
    }
}

// ---------------- main fused kernel ----------------
// smem layout (float index). A2 double-buffered: [m][kw], 36-word rows.
#define AB_O    0                     // 128: alpha|bshift
#define A2H0_O  128                   // 4032
#define A2L0_O  4160                  // 4032
#define A2H1_O  8192                  // 4032
#define A2L1_O  12224                 // 4032
#define XBH_O   16256                 // 16 x 265 = 4240
#define XBL_O   20496                 // 4240
#define SMEM_FLOATS 24736
#define SMEM_BYTES  (SMEM_FLOATS * 4) // 98944 -> 2 CTAs/SM

struct G1Ctx {
    uint32_t* xbh;
    uint32_t* xbl;
    int wid, lane;
};

// GEMM1 for subset s, writing A2 buffer (a2h/a2l). Packs per-nt to cap regs.
__device__ __forceinline__ void gemm1_subset(const G1Ctx& g, int s,
                                             uint32_t* a2h, uint32_t* a2l) {
    const int wid = g.wid, lane = g.lane;
    uint4 AH[2][2], AL[2][2];
#pragma unroll
    for (int mt = 0; mt < 2; mt++)
#pragma unroll
        for (int kt = 0; kt < 2; kt++) {
            AH[mt][kt] = __ldg(g_Af + ((((s * 2 + mt) * 2 + kt) * 2 + 0) * 32) + lane);
            AL[mt][kt] = __ldg(g_Af + ((((s * 2 + mt) * 2 + kt) * 2 + 1) * 32) + lane);
        }

#pragma unroll
    for (int nt = 0; nt < 4; nt++) {
        float d1[2][4];
#pragma unroll
        for (int i = 0; i < 2; i++)
#pragma unroll
            for (int q = 0; q < 4; q++) d1[i][q] = 0.0f;

        const int nn = wid * 32 + nt * 8 + (lane >> 2);
#pragma unroll
        for (int kt = 0; kt < 2; kt++) {
            const int rb = kt * 8 + (lane & 3);
            uint32_t bh0 = g.xbh[rb * XBS + nn];
            uint32_t bh1 = g.xbh[(rb + 4) * XBS + nn];
            uint32_t bl0 = g.xbl[rb * XBS + nn];
            uint32_t bl1 = g.xbl[(rb + 4) * XBS + nn];
#pragma unroll
            for (int mt = 0; mt < 2; mt++) {
                mma16816(d1[mt], (const uint32_t*)&AH[mt][kt], bh0, bh1);
                mma16816(d1[mt], (const uint32_t*)&AL[mt][kt], bh0, bh1);
                mma16816(d1[mt], (const uint32_t*)&AH[mt][kt], bl0, bl1);
            }
        }

        // pack this nt slice into A2 [m][kw]
        const int n0 = wid * 32 + nt * 8 + (lane & 3) * 2;
        const int cw = (n0 & 63) >> 1;
        const int tt = n0 >> 6;
#pragma unroll
        for (int mt = 0; mt < 2; mt++) {
            const int gm = mt * 16 + (lane >> 2);
            const float* dd = d1[mt];
            if (gm < V_) {
                int m2 = tt * 25 + gm;
                uint32_t h = packbf(dd[1], dd[0]);
                float r0 = dd[0] - __uint_as_float(h << 16);
                float r1 = dd[1] - __uint_as_float(h & 0xffff0000u);
                a2h[m2 * 36 + cw] = h;
                a2l[m2 * 36 + cw] = packbf(r1, r0);
            }
            if (gm + 8 < V_) {
                int m2 = tt * 25 + gm + 8;
                uint32_t h = packbf(dd[3], dd[2]);
                float r0 = dd[2] - __uint_as_float(h << 16);
                float r1 = dd[3] - __uint_as_float(h & 0xffff0000u);
                a2h[m2 * 36 + cw] = h;
                a2l[m2 * 36 + cw] = packbf(r1, r0);
            }
        }
    }
}

// GEMM2 for subset s reading A2 buffer at byte base abase_s (hi; +a2dlt = lo).
__device__ __forceinline__ void gemm2_subset(float acc[2][4][4], int s,
                                             uint32_t abase_s, uint32_t a2dlt,
                                             int wy, int wx, int lane) {
    const uint4* wfs = g_Wf + (s * 4) * 8 * 32 + lane;
#pragma unroll
    for (int kt = 0; kt < 4; kt++) {
        uint4 Bf[4];
#pragma unroll
        for (int j = 0; j < 4; j++)
            Bf[j] = __ldg(wfs + (kt * 8 + wx * 4 + j) * 32);

#pragma unroll
        for (int mti = 0; mti < 2; mti++) {
            if (!(wy == 3 && mti == 1)) {   // rows 112..127 dead
                const uint32_t abase =
                    abase_s + (uint32_t)((wy * 2 + mti) * 16 * 144 + kt * 32);
                uint32_t ah[4], al[4];
                ldsm_x4(ah, abase);
                ldsm_x4(al, abase + a2dlt);
#pragma unroll
                for (int j = 0; j < 4; j++) {
                    mma16816(acc[mti][j], ah, Bf[j].x, Bf[j].y);
                    mma16816(acc[mti][j], al, Bf[j].x, Bf[j].y);
                    mma16816(acc[mti][j], ah, Bf[j].z, Bf[j].w);
                }
            }
        }
    }
}

__global__ void __launch_bounds__(NTHREADS, 2)
unit_gcn_main(const float* __restrict__ x, float* __restrict__ out) {
    const int n  = blockIdx.y;
    const int bx = blockIdx.x;       // t-tile
    const int t0 = bx * TT;
    const int tid = threadIdx.x;
    const int wid = tid >> 5;
    const int lane = tid & 31;

    extern __shared__ float sm[];
    float* ab = sm + AB_O;
    uint32_t* xbh = (uint32_t*)(sm + XBH_O);
    uint32_t* xbl = (uint32_t*)(sm + XBL_O);

    // Stage BN constants
    if (tid < 128) ab[tid] = g_ab[tid];

    // Zero xb pad rows 13..15 (k = 26..31). Row 12 (k=24,25) is fully
    // written by the wp=12 staging stores (hi half packed as 0).
    for (int i = tid; i < 3 * XBS; i += NTHREADS) {
        xbh[13 * XBS + i] = 0u;
        xbl[13 * XBS + i] = 0u;
    }
    // NOTE: no barrier needed — staging below writes rows 0..12 only (disjoint).

    // Stage x tile as k-pair-packed bf16 hi/lo words for GEMM1 B.
    // Task = (c, tt, wp): pack (x[2wp], x[2wp+1]) into ONE word per buffer.
    // 3328 tasks = 13 per thread. STS.32 bank step 9 -> conflict-free.
    {
#pragma unroll
        for (int r = 0; r < 13; r++) {
            int q  = tid + NTHREADS * r;
            int c  = q / 52;
            int rm = q - c * 52;
            int tt = rm / 13;
            int wp = rm - tt * 13;
            const float* xr = x + (n * 64 + c) * 7500 + bx * 100 + tt * 25 + wp * 2;
            float v0 = __ldg(xr);
            float v1 = (wp < 12) ? __ldg(xr + 1) : 0.0f;
            uint32_t hw = packbf(v1, v0);
            float l0 = v0 - __uint_as_float(hw << 16);
            float l1 = v1 - __uint_as_float(hw & 0xffff0000u);
            uint32_t lw = packbf(l1, l0);
            int word = wp * XBS + tt * 64 + c;
            xbh[word] = hw;
            xbl[word] = lw;
        }
    }
    __syncthreads();

    const int wy = wid & 3;
    const int wx = wid >> 2;

    float acc[2][4][4];
#pragma unroll
    for (int i = 0; i < 2; i++)
#pragma unroll
        for (int j = 0; j < 4; j++)
#pragma unroll
            for (int q = 0; q < 4; q++) acc[i][j][q] = 0.0f;

    const uint32_t a2h0_u = smem_u32_of(sm + A2H0_O);
    const uint32_t a2dlt = (uint32_t)((A2L0_O - A2H0_O) * 4);
    const uint32_t a2buf = (uint32_t)((A2H1_O - A2H0_O) * 4);
    const uint32_t lds_lane_off = (uint32_t)((lane & 15) * 144 + (lane >> 4) * 16);

    G1Ctx g;
    g.xbh = xbh; g.xbl = xbl; g.wid = wid; g.lane = lane;
    uint32_t* a2h_b[2] = {(uint32_t*)(sm + A2H0_O), (uint32_t*)(sm + A2H1_O)};
    uint32_t* a2l_b[2] = {(uint32_t*)(sm + A2L0_O), (uint32_t*)(sm + A2L1_O)};

    // ---- software pipeline over subsets ----
    gemm1_subset(g, 0, a2h_b[0], a2l_b[0]);
    __syncthreads();                                   // A2(0) ready
#pragma unroll
    for (int s = 0; s < S_; s++) {
        if (s < S_ - 1)
            gemm1_subset(g, s + 1, a2h_b[(s + 1) & 1], a2l_b[(s + 1) & 1]);
        gemm2_subset(acc, s,
                     a2h0_u + ((s & 1) ? a2buf : 0u) + lds_lane_off,
                     a2dlt, wy, wx, lane);
        if (s < S_ - 1) __syncthreads();               // A2(s+1) ready; G2(s) reads done
    }

    // -------- Epilogue: BN + residual(from gmem, L2-hot) + relu, store ------
    const int nb = wx * 32 + (lane & 3) * 2;
    float alv[8], bsv[8];
#pragma unroll
    for (int j = 0; j < 4; j++) {
        alv[2 * j]     = ab[nb + j * 8];
        alv[2 * j + 1] = ab[nb + j * 8 + 1];
        bsv[2 * j]     = ab[64 + nb + j * 8];
        bsv[2 * j + 1] = ab[64 + nb + j * 8 + 1];
    }

#pragma unroll
    for (int mti = 0; mti < 2; mti++) {
#pragma unroll
        for (int half = 0; half < 2; half++) {
            int m = (wy * 2 + mti) * 16 + (lane >> 2) + half * 8;
            if (m < COLS) {
                int tt = m / 25;
                int w  = m - tt * 25;
                int base = n * 480000 + (t0 + tt) * 25 + w;
#pragma unroll
                for (int j = 0; j < 4; j++) {
                    int o0 = nb + j * 8;
                    float c0 = acc[mti][j][half * 2];
                    float c1 = acc[mti][j][half * 2 + 1];
                    float r0 = __ldg(x + base + o0 * 7500);
                    float r1 = __ldg(x + base + (o0 + 1) * 7500);
                    float y0 = fmaf(c0, alv[2 * j], bsv[2 * j]) + r0;
                    float y1 = fmaf(c1, alv[2 * j + 1], bsv[2 * j + 1]) + r1;
                    out[base + o0 * 7500]       = fmaxf(y0, 0.0f);
                    out[base + (o0 + 1) * 7500] = fmaxf(y1, 0.0f);
                }
            }
        }
    }
}

extern "C" void kernel_launch(void* const* d_in, const int* in_sizes, int n_in,
                              void* d_out, int out_size) {
    const float* x     = (const float*)d_in[0];
    const float* A     = (const float*)d_in[1];
    const float* PA1   = (const float*)d_in[2];
    const float* PA2   = (const float*)d_in[3];
    const float* Wc    = (const float*)d_in[4];
    const float* bc    = (const float*)d_in[5];
    const float* gamma = (const float*)d_in[6];
    const float* beta  = (const float*)d_in[7];
    const float* rmean = (const float*)d_in[8];
    const float* rvar  = (const float*)d_in[9];
    float* out = (float*)d_out;

    unit_gcn_prep<<<8, 256>>>(A, PA1, PA2, Wc, bc, gamma, beta, rmean, rvar);

    cudaFuncSetAttribute(unit_gcn_main,
                         cudaFuncAttributeMaxDynamicSharedMemorySize, SMEM_BYTES);
    dim3 grid(TBLK, N_);
    unit_gcn_main<<<grid, NTHREADS, SMEM_BYTES>>>(x, out);
}

// round 13
// speedup vs baseline: 1.4728x; 1.2526x over previous
#include <cuda_runtime.h>
#include <cuda_bf16.h>
#include <cuda_fp16.h>
#include <cstdint>

// Problem dims (fixed by the dataset)
#define N_   64
#define C_   64
#define T_   300
#define V_   25
#define S_   3
#define TT   4              // t positions per block
#define COLS 100            // TT*V_
#define TBLK 75             // T_/TT
#define NTHREADS 256

// xb row stride in 32-bit words (odd -> conflict-free word stores, step 9)
#define XBS  265

// -------- global folded parameters (written by prep kernel) --------
__device__ __align__(16) uint2 g_Wh[S_ * 4 * 8 * 32];   // W fp16 frags [s][kt][ntg][lane]
__device__ __align__(16) uint4 g_Af[S_ * 2 * 2 * 2 * 32]; // Ae^T fp16 frags [s][mt][kt][hl][lane]
__device__ __align__(16) float g_ab[128];                // alpha | bshift

// ---------------- fp16 / mma helpers ----------------
// packhf(hi_elem, lo_elem): low 16 bits = f16(lo_elem)  (same cvt convention as bf16, verified R5)
__device__ __forceinline__ uint32_t packhf(float hi, float lo) {
    uint32_t d;
    asm("cvt.rn.f16x2.f32 %0, %1, %2;" : "=r"(d) : "f"(hi), "f"(lo));
    return d;
}
__device__ __forceinline__ float2 h2f2(uint32_t w) {
    __half2 h = *reinterpret_cast<__half2*>(&w);   // .x = low half
    return __half22float2(h);
}
__device__ __forceinline__ void mma16816f(float* c, const uint32_t* a,
                                          uint32_t b0, uint32_t b1) {
    asm volatile(
        "mma.sync.aligned.m16n8k16.row.col.f32.f16.f16.f32 "
        "{%0,%1,%2,%3}, {%4,%5,%6,%7}, {%8,%9}, {%0,%1,%2,%3};"
        : "+f"(c[0]), "+f"(c[1]), "+f"(c[2]), "+f"(c[3])
        : "r"(a[0]), "r"(a[1]), "r"(a[2]), "r"(a[3]), "r"(b0), "r"(b1));
}
__device__ __forceinline__ void ldsm_x4(uint32_t* r, uint32_t addr) {
    asm volatile(
        "ldmatrix.sync.aligned.m8n8.x4.shared.b16 {%0,%1,%2,%3}, [%4];"
        : "=r"(r[0]), "=r"(r[1]), "=r"(r[2]), "=r"(r[3]) : "r"(addr));
}
__device__ __forceinline__ uint32_t smem_u32_of(const void* p) {
    uint32_t a;
    asm("{ .reg .u64 t; cvta.to.shared.u64 t, %1; cvt.u32.u64 %0, t; }"
        : "=r"(a) : "l"(p));
    return a;
}

// ---------------- prep: fold params (tiny, few blocks) ----------------
__global__ void unit_gcn_prep(const float* __restrict__ pA,
                              const float* __restrict__ pPA1,
                              const float* __restrict__ pPA2,
                              const float* __restrict__ pWc,
                              const float* __restrict__ pbc,
                              const float* __restrict__ pgamma,
                              const float* __restrict__ pbeta,
                              const float* __restrict__ prmean,
                              const float* __restrict__ prvar) {
    int tid = blockIdx.x * blockDim.x + threadIdx.x;

    // W fp16 fragments for GEMM2 B operand (col-major KxN). Hi only —
    // the W-residual chain is dropped (error ~2^-11, inside budget).
    for (int i = tid; i < S_ * 4 * 8 * 32; i += blockDim.x * gridDim.x) {
        int lane = i & 31;
        int ntg  = (i >> 5) & 7;
        int kt   = (i >> 8) & 3;
        int s    = i >> 10;
        int n  = ntg * 8 + (lane >> 2);
        int k0 = kt * 16 + (lane & 3) * 2;
        const float* wr = pWc + (s * 64 + n) * 64;
        uint2 frag;
        frag.x = packhf(wr[k0 + 1], wr[k0]);
        frag.y = packhf(wr[k0 + 9], wr[k0 + 8]);
        g_Wh[i] = frag;
    }

    // Ae^T fp16 fragments for GEMM1 A operand (row-major 32x32), hi + residual.
    for (int i = tid; i < S_ * 2 * 2 * 2 * 32; i += blockDim.x * gridDim.x) {
        int lane = i & 31;
        int hl = (i >> 5) & 1;
        int kt = (i >> 6) & 1;
        int mt = (i >> 7) & 1;
        int s  = i >> 8;
        int gm = mt * 16 + (lane >> 2);
        int k0 = kt * 16 + (lane & 3) * 2;
        float e[8];
        int ms[2] = {gm, gm + 8};
        int ks[4] = {k0, k0 + 1, k0 + 8, k0 + 9};
#pragma unroll
        for (int kk = 0; kk < 4; kk++)
#pragma unroll
            for (int mm = 0; mm < 2; mm++) {
                int m = ms[mm], k = ks[kk];
                float v = 0.0f;
                if (m < V_ && k < V_) {
                    int idx = (s * V_ + k) * V_ + m;
                    v = pA[idx] * pPA1[idx] + pPA2[idx];
                }
                e[kk * 2 + mm] = v;
            }
        if (hl) {
#pragma unroll
            for (int q = 0; q < 8; q++) {
                float h = __half2float(__float2half_rn(e[q]));
                e[q] = e[q] - h;
            }
        }
        uint4 frag;
        frag.x = packhf(e[2], e[0]);
        frag.y = packhf(e[3], e[1]);
        frag.z = packhf(e[6], e[4]);
        frag.w = packhf(e[7], e[5]);
        g_Af[i] = frag;
    }

    // BN fold: out = gemm*alpha + bshift (+x, relu). Bias folded into bshift.
    if (tid < C_) {
        float sc = pgamma[tid] / sqrtf(prvar[tid] + 1e-5f);
        float btot = pbc[tid] + pbc[64 + tid] + pbc[128 + tid];
        g_ab[tid] = sc;
        g_ab[64 + tid] = btot * sc + (pbeta[tid] - prmean[tid] * sc);
    }
}

// ---------------- main fused kernel ----------------
// smem layout (float index). A2 double-buffered: [m][kw], 36-word rows.
#define AB_O    0                     // 128: alpha|bshift
#define A2H0_O  128                   // 4032
#define A2L0_O  4160                  // 4032
#define A2H1_O  8192                  // 4032
#define A2L1_O  12224                 // 4032
#define XBH_O   16256                 // 16 x 265 = 4240 (fp16 x, k-pair packed)
#define SMEM_FLOATS 20496
#define SMEM_BYTES  (SMEM_FLOATS * 4) // 81984 -> 2 CTAs/SM

struct G1Ctx {
    uint32_t* xbh;
    int wid, lane;
};

// GEMM1 for subset s, writing A2 buffer (a2h/a2l). fp16, 2 chains.
__device__ __forceinline__ void gemm1_subset(const G1Ctx& g, int s,
                                             uint32_t* a2h, uint32_t* a2l) {
    const int wid = g.wid, lane = g.lane;
    uint4 AH[2][2], AL[2][2];
#pragma unroll
    for (int mt = 0; mt < 2; mt++)
#pragma unroll
        for (int kt = 0; kt < 2; kt++) {
            AH[mt][kt] = __ldg(g_Af + ((((s * 2 + mt) * 2 + kt) * 2 + 0) * 32) + lane);
            AL[mt][kt] = __ldg(g_Af + ((((s * 2 + mt) * 2 + kt) * 2 + 1) * 32) + lane);
        }

#pragma unroll
    for (int nt = 0; nt < 4; nt++) {
        float d1[2][4];
#pragma unroll
        for (int i = 0; i < 2; i++)
#pragma unroll
            for (int q = 0; q < 4; q++) d1[i][q] = 0.0f;

        const int nn = wid * 32 + nt * 8 + (lane >> 2);
#pragma unroll
        for (int kt = 0; kt < 2; kt++) {
            const int rb = kt * 8 + (lane & 3);
            uint32_t bh0 = g.xbh[rb * XBS + nn];
            uint32_t bh1 = g.xbh[(rb + 4) * XBS + nn];
#pragma unroll
            for (int mt = 0; mt < 2; mt++) {
                mma16816f(d1[mt], (const uint32_t*)&AH[mt][kt], bh0, bh1);
                mma16816f(d1[mt], (const uint32_t*)&AL[mt][kt], bh0, bh1);
            }
        }

        // pack this nt slice into A2 [m][kw] as fp16 hi + residual
        const int n0 = wid * 32 + nt * 8 + (lane & 3) * 2;
        const int cw = (n0 & 63) >> 1;
        const int tt = n0 >> 6;
#pragma unroll
        for (int mt = 0; mt < 2; mt++) {
            const int gm = mt * 16 + (lane >> 2);
            const float* dd = d1[mt];
            if (gm < V_) {
                int m2 = tt * 25 + gm;
                uint32_t h = packhf(dd[1], dd[0]);
                float2 hf = h2f2(h);
                a2h[m2 * 36 + cw] = h;
                a2l[m2 * 36 + cw] = packhf(dd[1] - hf.y, dd[0] - hf.x);
            }
            if (gm + 8 < V_) {
                int m2 = tt * 25 + gm + 8;
                uint32_t h = packhf(dd[3], dd[2]);
                float2 hf = h2f2(h);
                a2h[m2 * 36 + cw] = h;
                a2l[m2 * 36 + cw] = packhf(dd[3] - hf.y, dd[2] - hf.x);
            }
        }
    }
}

// GEMM2 for subset s reading A2 buffer at byte base abase_s (hi; +a2dlt = lo).
__device__ __forceinline__ void gemm2_subset(float acc[2][4][4], int s,
                                             uint32_t abase_s, uint32_t a2dlt,
                                             int wy, int wx, int lane) {
    const uint2* wfs = g_Wh + (s * 4) * 8 * 32 + lane;
#pragma unroll
    for (int kt = 0; kt < 4; kt++) {
        uint2 Bf[4];
#pragma unroll
        for (int j = 0; j < 4; j++)
            Bf[j] = __ldg(wfs + (kt * 8 + wx * 4 + j) * 32);

#pragma unroll
        for (int mti = 0; mti < 2; mti++) {
            if (!(wy == 3 && mti == 1)) {   // rows 112..127 dead
                const uint32_t abase =
                    abase_s + (uint32_t)((wy * 2 + mti) * 16 * 144 + kt * 32);
                uint32_t ah[4], al[4];
                ldsm_x4(ah, abase);
                ldsm_x4(al, abase + a2dlt);
#pragma unroll
                for (int j = 0; j < 4; j++) {
                    mma16816f(acc[mti][j], ah, Bf[j].x, Bf[j].y);
                    mma16816f(acc[mti][j], al, Bf[j].x, Bf[j].y);
                }
            }
        }
    }
}

__global__ void __launch_bounds__(NTHREADS, 2)
unit_gcn_main(const float* __restrict__ x, float* __restrict__ out) {
    const int n  = blockIdx.y;
    const int bx = blockIdx.x;       // t-tile
    const int t0 = bx * TT;
    const int tid = threadIdx.x;
    const int wid = tid >> 5;
    const int lane = tid & 31;

    extern __shared__ float sm[];
    float* ab = sm + AB_O;
    uint32_t* xbh = (uint32_t*)(sm + XBH_O);

    // Stage BN constants
    if (tid < 128) ab[tid] = g_ab[tid];

    // Zero xb pad rows 13..15 (k = 26..31). Row 12 (k=24,25): wp=12 packs 0 hi.
    for (int i = tid; i < 3 * XBS; i += NTHREADS) {
        xbh[13 * XBS + i] = 0u;
    }
    // staging below writes rows 0..12 only (disjoint) — no barrier needed.

    // Stage x tile as k-pair-packed fp16 words for GEMM1 B (hi only).
    {
#pragma unroll
        for (int r = 0; r < 13; r++) {
            int q  = tid + NTHREADS * r;
            int c  = q / 52;
            int rm = q - c * 52;
            int tt = rm / 13;
            int wp = rm - tt * 13;
            const float* xr = x + (n * 64 + c) * 7500 + bx * 100 + tt * 25 + wp * 2;
            float v0 = __ldg(xr);
            float v1 = (wp < 12) ? __ldg(xr + 1) : 0.0f;
            xbh[wp * XBS + tt * 64 + c] = packhf(v1, v0);
        }
    }
    __syncthreads();

    const int wy = wid & 3;
    const int wx = wid >> 2;

    float acc[2][4][4];
#pragma unroll
    for (int i = 0; i < 2; i++)
#pragma unroll
        for (int j = 0; j < 4; j++)
#pragma unroll
            for (int q = 0; q < 4; q++) acc[i][j][q] = 0.0f;

    const uint32_t a2h0_u = smem_u32_of(sm + A2H0_O);
    const uint32_t a2dlt = (uint32_t)((A2L0_O - A2H0_O) * 4);
    const uint32_t a2buf = (uint32_t)((A2H1_O - A2H0_O) * 4);
    const uint32_t lds_lane_off = (uint32_t)((lane & 15) * 144 + (lane >> 4) * 16);

    G1Ctx g;
    g.xbh = xbh; g.wid = wid; g.lane = lane;
    uint32_t* a2h_b[2] = {(uint32_t*)(sm + A2H0_O), (uint32_t*)(sm + A2H1_O)};
    uint32_t* a2l_b[2] = {(uint32_t*)(sm + A2L0_O), (uint32_t*)(sm + A2L1_O)};

    // ---- software pipeline over subsets ----
    gemm1_subset(g, 0, a2h_b[0], a2l_b[0]);
    __syncthreads();                                   // A2(0) ready
#pragma unroll
    for (int s = 0; s < S_; s++) {
        if (s < S_ - 1)
            gemm1_subset(g, s + 1, a2h_b[(s + 1) & 1], a2l_b[(s + 1) & 1]);
        gemm2_subset(acc, s,
                     a2h0_u + ((s & 1) ? a2buf : 0u) + lds_lane_off,
                     a2dlt, wy, wx, lane);
        if (s < S_ - 1) __syncthreads();               // A2(s+1) ready; G2(s) reads done
    }

    // -------- Epilogue: BN + residual(from gmem, L2-hot) + relu, store ------
    const int nb = wx * 32 + (lane & 3) * 2;
    float alv[8], bsv[8];
#pragma unroll
    for (int j = 0; j < 4; j++) {
        alv[2 * j]     = ab[nb + j * 8];
        alv[2 * j + 1] = ab[nb + j * 8 + 1];
        bsv[2 * j]     = ab[64 + nb + j * 8];
        bsv[2 * j + 1] = ab[64 + nb + j * 8 + 1];
    }

#pragma unroll
    for (int mti = 0; mti < 2; mti++) {
#pragma unroll
        for (int half = 0; half < 2; half++) {
            int m = (wy * 2 + mti) * 16 + (lane >> 2) + half * 8;
            if (m < COLS) {
                int tt = m / 25;
                int w  = m - tt * 25;
                int base = n * 480000 + (t0 + tt) * 25 + w;
#pragma unroll
                for (int j = 0; j < 4; j++) {
                    int o0 = nb + j * 8;
                    float c0 = acc[mti][j][half * 2];
                    float c1 = acc[mti][j][half * 2 + 1];
                    float r0 = __ldg(x + base + o0 * 7500);
                    float r1 = __ldg(x + base + (o0 + 1) * 7500);
                    float y0 = fmaf(c0, alv[2 * j], bsv[2 * j]) + r0;
                    float y1 = fmaf(c1, alv[2 * j + 1], bsv[2 * j + 1]) + r1;
                    out[base + o0 * 7500]       = fmaxf(y0, 0.0f);
                    out[base + (o0 + 1) * 7500] = fmaxf(y1, 0.0f);
                }
            }
        }
    }
}

extern "C" void kernel_launch(void* const* d_in, const int* in_sizes, int n_in,
                              void* d_out, int out_size) {
    const float* x     = (const float*)d_in[0];
    const float* A     = (const float*)d_in[1];
    const float* PA1   = (const float*)d_in[2];
    const float* PA2   = (const float*)d_in[3];
    const float* Wc    = (const float*)d_in[4];
    const float* bc    = (const float*)d_in[5];
    const float* gamma = (const float*)d_in[6];
    const float* beta  = (const float*)d_in[7];
    const float* rmean = (const float*)d_in[8];
    const float* rvar  = (const float*)d_in[9];
    float* out = (float*)d_out;

    unit_gcn_prep<<<8, 256>>>(A, PA1, PA2, Wc, bc, gamma, beta, rmean, rvar);

    cudaFuncSetAttribute(unit_gcn_main,
                         cudaFuncAttributeMaxDynamicSharedMemorySize, SMEM_BYTES);
    dim3 grid(TBLK, N_);
    unit_gcn_main<<<grid, NTHREADS, SMEM_BYTES>>>(x, out);
}

// round 14
// speedup vs baseline: 1.8472x; 1.2542x over previous
#include <cuda_runtime.h>
#include <cuda_bf16.h>
#include <cuda_fp16.h>
#include <cstdint>

// Problem dims (fixed by the dataset)
#define N_   64
#define C_   64
#define T_   300
#define V_   25
#define S_   3
#define TT   4              // t positions per block
#define COLS 100            // TT*V_
#define TBLK 75             // T_/TT
#define NTHREADS 256

// xb row stride in 32-bit words (odd -> conflict-free word stores, step 9)
#define XBS  265

// -------- global folded parameters (written by prep kernel) --------
__device__ __align__(16) uint2 g_Wh[S_ * 4 * 8 * 32];   // W fp16 frags [s][kt][ntg][lane]
__device__ __align__(16) uint4 g_Af[S_ * 2 * 2 * 2 * 32]; // Ae^T fp16 frags [s][mt][kt][hl][lane]
__device__ __align__(16) float g_ab[128];                // alpha | bshift

// ---------------- fp16 / mma helpers ----------------
// packhf(hi_elem, lo_elem): low 16 bits = f16(lo_elem)
__device__ __forceinline__ uint32_t packhf(float hi, float lo) {
    uint32_t d;
    asm("cvt.rn.f16x2.f32 %0, %1, %2;" : "=r"(d) : "f"(hi), "f"(lo));
    return d;
}
__device__ __forceinline__ void mma16816f(float* c, const uint32_t* a,
                                          uint32_t b0, uint32_t b1) {
    asm volatile(
        "mma.sync.aligned.m16n8k16.row.col.f32.f16.f16.f32 "
        "{%0,%1,%2,%3}, {%4,%5,%6,%7}, {%8,%9}, {%0,%1,%2,%3};"
        : "+f"(c[0]), "+f"(c[1]), "+f"(c[2]), "+f"(c[3])
        : "r"(a[0]), "r"(a[1]), "r"(a[2]), "r"(a[3]), "r"(b0), "r"(b1));
}
__device__ __forceinline__ void ldsm_x4(uint32_t* r, uint32_t addr) {
    asm volatile(
        "ldmatrix.sync.aligned.m8n8.x4.shared.b16 {%0,%1,%2,%3}, [%4];"
        : "=r"(r[0]), "=r"(r[1]), "=r"(r[2]), "=r"(r[3]) : "r"(addr));
}
__device__ __forceinline__ uint32_t smem_u32_of(const void* p) {
    uint32_t a;
    asm("{ .reg .u64 t; cvta.to.shared.u64 t, %1; cvt.u32.u64 %0, t; }"
        : "=r"(a) : "l"(p));
    return a;
}

// ---------------- prep: fold params (tiny, few blocks) ----------------
__global__ void unit_gcn_prep(const float* __restrict__ pA,
                              const float* __restrict__ pPA1,
                              const float* __restrict__ pPA2,
                              const float* __restrict__ pWc,
                              const float* __restrict__ pbc,
                              const float* __restrict__ pgamma,
                              const float* __restrict__ pbeta,
                              const float* __restrict__ prmean,
                              const float* __restrict__ prvar) {
    int tid = blockIdx.x * blockDim.x + threadIdx.x;

    // W fp16 fragments for GEMM2 B operand (col-major KxN). Hi only.
    for (int i = tid; i < S_ * 4 * 8 * 32; i += blockDim.x * gridDim.x) {
        int lane = i & 31;
        int ntg  = (i >> 5) & 7;
        int kt   = (i >> 8) & 3;
        int s    = i >> 10;
        int n  = ntg * 8 + (lane >> 2);
        int k0 = kt * 16 + (lane & 3) * 2;
        const float* wr = pWc + (s * 64 + n) * 64;
        uint2 frag;
        frag.x = packhf(wr[k0 + 1], wr[k0]);
        frag.y = packhf(wr[k0 + 9], wr[k0 + 8]);
        g_Wh[i] = frag;
    }

    // Ae^T fp16 fragments for GEMM1 A operand (row-major 32x32), hi + residual.
    for (int i = tid; i < S_ * 2 * 2 * 2 * 32; i += blockDim.x * gridDim.x) {
        int lane = i & 31;
        int hl = (i >> 5) & 1;
        int kt = (i >> 6) & 1;
        int mt = (i >> 7) & 1;
        int s  = i >> 8;
        int gm = mt * 16 + (lane >> 2);
        int k0 = kt * 16 + (lane & 3) * 2;
        float e[8];
        int ms[2] = {gm, gm + 8};
        int ks[4] = {k0, k0 + 1, k0 + 8, k0 + 9};
#pragma unroll
        for (int kk = 0; kk < 4; kk++)
#pragma unroll
            for (int mm = 0; mm < 2; mm++) {
                int m = ms[mm], k = ks[kk];
                float v = 0.0f;
                if (m < V_ && k < V_) {
                    int idx = (s * V_ + k) * V_ + m;
                    v = pA[idx] * pPA1[idx] + pPA2[idx];
                }
                e[kk * 2 + mm] = v;
            }
        if (hl) {
#pragma unroll
            for (int q = 0; q < 8; q++) {
                float h = __half2float(__float2half_rn(e[q]));
                e[q] = e[q] - h;
            }
        }
        uint4 frag;
        frag.x = packhf(e[2], e[0]);
        frag.y = packhf(e[3], e[1]);
        frag.z = packhf(e[6], e[4]);
        frag.w = packhf(e[7], e[5]);
        g_Af[i] = frag;
    }

    // BN fold: out = gemm*alpha + bshift (+x, relu). Bias folded into bshift.
    if (tid < C_) {
        float sc = pgamma[tid] / sqrtf(prvar[tid] + 1e-5f);
        float btot = pbc[tid] + pbc[64 + tid] + pbc[128 + tid];
        g_ab[tid] = sc;
        g_ab[64 + tid] = btot * sc + (pbeta[tid] - prmean[tid] * sc);
    }
}

// ---------------- main fused kernel ----------------
// smem layout (float index). A2 (hi only) double-buffered: [m][kw], 36-word rows.
#define AB_O    0                     // 128: alpha|bshift
#define A2H0_O  128                   // 4032
#define A2H1_O  4224                  // 4032 (64-word pad between buffers)
#define XBH_O   8320                  // 16 x 265 = 4240 (fp16 x, k-pair packed)
#define SMEM_FLOATS 12560
#define SMEM_BYTES  (SMEM_FLOATS * 4) // 50240 -> 2 CTAs/SM (reg-bound anyway)

struct G1Ctx {
    uint32_t* xbh;
    int wid, lane;
};

// GEMM1 for subset s, writing A2 hi buffer. fp16, 2 chains (Ae hi+lo).
__device__ __forceinline__ void gemm1_subset(const G1Ctx& g, int s,
                                             uint32_t* a2h) {
    const int wid = g.wid, lane = g.lane;
    uint4 AH[2][2], AL[2][2];
#pragma unroll
    for (int mt = 0; mt < 2; mt++)
#pragma unroll
        for (int kt = 0; kt < 2; kt++) {
            AH[mt][kt] = __ldg(g_Af + ((((s * 2 + mt) * 2 + kt) * 2 + 0) * 32) + lane);
            AL[mt][kt] = __ldg(g_Af + ((((s * 2 + mt) * 2 + kt) * 2 + 1) * 32) + lane);
        }

#pragma unroll
    for (int nt = 0; nt < 4; nt++) {
        float d1[2][4];
#pragma unroll
        for (int i = 0; i < 2; i++)
#pragma unroll
            for (int q = 0; q < 4; q++) d1[i][q] = 0.0f;

        const int nn = wid * 32 + nt * 8 + (lane >> 2);
#pragma unroll
        for (int kt = 0; kt < 2; kt++) {
            const int rb = kt * 8 + (lane & 3);
            uint32_t bh0 = g.xbh[rb * XBS + nn];
            uint32_t bh1 = g.xbh[(rb + 4) * XBS + nn];
#pragma unroll
            for (int mt = 0; mt < 2; mt++) {
                mma16816f(d1[mt], (const uint32_t*)&AH[mt][kt], bh0, bh1);
                mma16816f(d1[mt], (const uint32_t*)&AL[mt][kt], bh0, bh1);
            }
        }

        // pack this nt slice into A2 [m][kw] as fp16 hi (lo chain dropped)
        const int n0 = wid * 32 + nt * 8 + (lane & 3) * 2;
        const int cw = (n0 & 63) >> 1;
        const int tt = n0 >> 6;
#pragma unroll
        for (int mt = 0; mt < 2; mt++) {
            const int gm = mt * 16 + (lane >> 2);
            const float* dd = d1[mt];
            if (gm < V_) {
                int m2 = tt * 25 + gm;
                a2h[m2 * 36 + cw] = packhf(dd[1], dd[0]);
            }
            if (gm + 8 < V_) {
                int m2 = tt * 25 + gm + 8;
                a2h[m2 * 36 + cw] = packhf(dd[3], dd[2]);
            }
        }
    }
}

// GEMM2 for subset s reading A2 hi buffer at byte base abase_s.
__device__ __forceinline__ void gemm2_subset(float acc[2][4][4], int s,
                                             uint32_t abase_s,
                                             int wy, int wx, int lane) {
    const uint2* wfs = g_Wh + (s * 4) * 8 * 32 + lane;
#pragma unroll
    for (int kt = 0; kt < 4; kt++) {
        uint2 Bf[4];
#pragma unroll
        for (int j = 0; j < 4; j++)
            Bf[j] = __ldg(wfs + (kt * 8 + wx * 4 + j) * 32);

#pragma unroll
        for (int mti = 0; mti < 2; mti++) {
            if (!(wy == 3 && mti == 1)) {   // rows 112..127 dead
                const uint32_t abase =
                    abase_s + (uint32_t)((wy * 2 + mti) * 16 * 144 + kt * 32);
                uint32_t ah[4];
                ldsm_x4(ah, abase);
#pragma unroll
                for (int j = 0; j < 4; j++)
                    mma16816f(acc[mti][j], ah, Bf[j].x, Bf[j].y);
            }
        }
    }
}

__global__ void __launch_bounds__(NTHREADS, 2)
unit_gcn_main(const float* __restrict__ x, float* __restrict__ out) {
    const int n  = blockIdx.y;
    const int bx = blockIdx.x;       // t-tile
    const int t0 = bx * TT;
    const int tid = threadIdx.x;
    const int wid = tid >> 5;
    const int lane = tid & 31;

    extern __shared__ float sm[];
    float* ab = sm + AB_O;
    uint32_t* xbh = (uint32_t*)(sm + XBH_O);

    // Stage BN constants
    if (tid < 128) ab[tid] = g_ab[tid];

    // Zero xb pad rows 13..15 (k = 26..31). Row 12 (k=24,25): wp=12 packs 0 hi.
    for (int i = tid; i < 3 * XBS; i += NTHREADS) {
        xbh[13 * XBS + i] = 0u;
    }
    // staging below writes rows 0..12 only (disjoint) — no barrier needed.

    // Stage x tile as k-pair-packed fp16 words for GEMM1 B (hi only).
    {
#pragma unroll
        for (int r = 0; r < 13; r++) {
            int q  = tid + NTHREADS * r;
            int c  = q / 52;
            int rm = q - c * 52;
            int tt = rm / 13;
            int wp = rm - tt * 13;
            const float* xr = x + (n * 64 + c) * 7500 + bx * 100 + tt * 25 + wp * 2;
            float v0 = __ldg(xr);
            float v1 = (wp < 12) ? __ldg(xr + 1) : 0.0f;
            xbh[wp * XBS + tt * 64 + c] = packhf(v1, v0);
        }
    }
    __syncthreads();

    const int wy = wid & 3;
    const int wx = wid >> 2;

    float acc[2][4][4];
#pragma unroll
    for (int i = 0; i < 2; i++)
#pragma unroll
        for (int j = 0; j < 4; j++)
#pragma unroll
            for (int q = 0; q < 4; q++) acc[i][j][q] = 0.0f;

    const uint32_t a2h0_u = smem_u32_of(sm + A2H0_O);
    const uint32_t a2buf = (uint32_t)((A2H1_O - A2H0_O) * 4);
    const uint32_t lds_lane_off = (uint32_t)((lane & 15) * 144 + (lane >> 4) * 16);

    G1Ctx g;
    g.xbh = xbh; g.wid = wid; g.lane = lane;
    uint32_t* a2h_b[2] = {(uint32_t*)(sm + A2H0_O), (uint32_t*)(sm + A2H1_O)};

    // ---- software pipeline over subsets ----
    gemm1_subset(g, 0, a2h_b[0]);
    __syncthreads();                                   // A2(0) ready
#pragma unroll
    for (int s = 0; s < S_; s++) {
        if (s < S_ - 1)
            gemm1_subset(g, s + 1, a2h_b[(s + 1) & 1]);
        gemm2_subset(acc, s,
                     a2h0_u + ((s & 1) ? a2buf : 0u) + lds_lane_off,
                     wy, wx, lane);
        if (s < S_ - 1) __syncthreads();               // A2(s+1) ready; G2(s) reads done
    }

    // -------- Epilogue: BN + residual(from gmem, L2-hot) + relu, store ------
    const int nb = wx * 32 + (lane & 3) * 2;
    float alv[8], bsv[8];
#pragma unroll
    for (int j = 0; j < 4; j++) {
        alv[2 * j]     = ab[nb + j * 8];
        alv[2 * j + 1] = ab[nb + j * 8 + 1];
        bsv[2 * j]     = ab[64 + nb + j * 8];
        bsv[2 * j + 1] = ab[64 + nb + j * 8 + 1];
    }

#pragma unroll
    for (int mti = 0; mti < 2; mti++) {
#pragma unroll
        for (int half = 0; half < 2; half++) {
            int m = (wy * 2 + mti) * 16 + (lane >> 2) + half * 8;
            if (m < COLS) {
                int tt = m / 25;
                int w  = m - tt * 25;
                int base = n * 480000 + (t0 + tt) * 25 + w;
#pragma unroll
                for (int j = 0; j < 4; j++) {
                    int o0 = nb + j * 8;
                    float c0 = acc[mti][j][half * 2];
                    float c1 = acc[mti][j][half * 2 + 1];
                    float r0 = __ldg(x + base + o0 * 7500);
                    float r1 = __ldg(x + base + (o0 + 1) * 7500);
                    float y0 = fmaf(c0, alv[2 * j], bsv[2 * j]) + r0;
                    float y1 = fmaf(c1, alv[2 * j + 1], bsv[2 * j + 1]) + r1;
                    out[base + o0 * 7500]       = fmaxf(y0, 0.0f);
                    out[base + (o0 + 1) * 7500] = fmaxf(y1, 0.0f);
                }
            }
        }
    }
}

extern "C" void kernel_launch(void* const* d_in, const int* in_sizes, int n_in,
                              void* d_out, int out_size) {
    const float* x     = (const float*)d_in[0];
    const float* A     = (const float*)d_in[1];
    const float* PA1   = (const float*)d_in[2];
    const float* PA2   = (const float*)d_in[3];
    const float* Wc    = (const float*)d_in[4];
    const float* bc    = (const float*)d_in[5];
    const float* gamma = (const float*)d_in[6];
    const float* beta  = (const float*)d_in[7];
    const float* rmean = (const float*)d_in[8];
    const float* rvar  = (const float*)d_in[9];
    float* out = (float*)d_out;

    unit_gcn_prep<<<8, 256>>>(A, PA1, PA2, Wc, bc, gamma, beta, rmean, rvar);

    cudaFuncSetAttribute(unit_gcn_main,
                         cudaFuncAttributeMaxDynamicSharedMemorySize, SMEM_BYTES);
    dim3 grid(TBLK, N_);
    unit_gcn_main<<<grid, NTHREADS, SMEM_BYTES>>>(x, out);
}